// round 4
// baseline (speedup 1.0000x reference)
#include <cuda_runtime.h>
#include <math.h>

#define BSZ 4
#define SEQ 2048
#define EMB 512
#define HEADS 8
#define HD 64
#define HH 512
#define MROWS (BSZ*SEQ)   // 8192
#define NEGINF (-1e30f)

// Scratch (device globals — no allocation allowed)
__device__ float g_q[MROWS*HH];
__device__ float g_k[MROWS*HH];
__device__ float g_v[MROWS*HH];
__device__ float g_att[MROWS*HH];

// ---------------------------------------------------------------------------
// fp32 tiled GEMM: C[M,Nn] = alpha * A[M,K] @ B[K,Nn] (+ bias[n])
// BM=BN=128, BK=8, 256 threads, 8x8 microtile per thread.
// M,Nn multiples of 128; K multiple of 8 (true for all uses here).
// ---------------------------------------------------------------------------
__global__ void __launch_bounds__(256) gemm128(
    const float* __restrict__ A, const float* __restrict__ B,
    float* __restrict__ C, int M, int Nn, int K,
    float alpha, const float* __restrict__ bias)
{
    __shared__ float As[8][128];
    __shared__ float Bs[8][128];

    const int tid = threadIdx.x;
    const int tx = tid & 15;        // 0..15  (col group)
    const int ty = tid >> 4;        // 0..15  (row group)
    const int rm = blockIdx.y * 128;
    const int cn = blockIdx.x * 128;

    // A-tile loader: thread -> (row, 4-col segment)
    const int ar  = tid >> 1;            // 0..127
    const int ac4 = (tid & 1) * 4;       // 0 or 4
    // B-tile loader: thread -> (row, 4-col segment)
    const int br  = tid >> 5;            // 0..7
    const int bc4 = (tid & 31) * 4;      // 0..124

    const float* Aptr = A + (size_t)(rm + ar) * K + ac4;
    const float* Bptr = B + (size_t)br * Nn + cn + bc4;

    float acc[8][8];
    #pragma unroll
    for (int i = 0; i < 8; i++)
        #pragma unroll
        for (int j = 0; j < 8; j++) acc[i][j] = 0.f;

    for (int kk = 0; kk < K; kk += 8) {
        float4 av = *(const float4*)(Aptr + kk);
        float4 bv = *(const float4*)(Bptr + (size_t)kk * Nn);
        // store A transposed for coalesced compute reads
        As[ac4 + 0][ar] = av.x;
        As[ac4 + 1][ar] = av.y;
        As[ac4 + 2][ar] = av.z;
        As[ac4 + 3][ar] = av.w;
        *(float4*)&Bs[br][bc4] = bv;
        __syncthreads();

        #pragma unroll
        for (int k = 0; k < 8; k++) {
            float a[8], b[8];
            *(float4*)&a[0] = *(const float4*)&As[k][ty * 8];
            *(float4*)&a[4] = *(const float4*)&As[k][ty * 8 + 4];
            *(float4*)&b[0] = *(const float4*)&Bs[k][tx * 8];
            *(float4*)&b[4] = *(const float4*)&Bs[k][tx * 8 + 4];
            #pragma unroll
            for (int i = 0; i < 8; i++)
                #pragma unroll
                for (int j = 0; j < 8; j++)
                    acc[i][j] = fmaf(a[i], b[j], acc[i][j]);
        }
        __syncthreads();
    }

    #pragma unroll
    for (int i = 0; i < 8; i++) {
        const int row = rm + ty * 8 + i;
        #pragma unroll
        for (int j = 0; j < 8; j += 4) {
            const int col = cn + tx * 8 + j;
            float4 o;
            o.x = acc[i][j + 0] * alpha;
            o.y = acc[i][j + 1] * alpha;
            o.z = acc[i][j + 2] * alpha;
            o.w = acc[i][j + 3] * alpha;
            if (bias) {
                o.x += bias[col + 0];
                o.y += bias[col + 1];
                o.z += bias[col + 2];
                o.w += bias[col + 3];
            }
            *(float4*)(C + (size_t)row * Nn + col) = o;
        }
    }
}

// ---------------------------------------------------------------------------
// Sparse masked attention.
// Mask for query q: keys {q-64 .. q} (local, diff 0..64) U {q-64m, m>=2} (strided).
// One block per (qtile of 64, head, batch). One warp per query (8 warps,
// each warp does 8 queries). 128-key window staged in shared; strided keys
// gathered from global (L2-resident).
// ---------------------------------------------------------------------------
#define ATTN_SMEM ((64*64 + 128*65 + 128*64) * 4)

__global__ void __launch_bounds__(256) attn_kernel(
    const float* __restrict__ q, const float* __restrict__ k,
    const float* __restrict__ v, float* __restrict__ out)
{
    extern __shared__ float sm[];
    float* sq = sm;                  // [64][64]
    float* sk = sm + 64 * 64;        // [128][65]  (padded: conflict-free per-lane dots)
    float* sv = sk + 128 * 65;       // [128][64]

    const int qt   = blockIdx.x;     // 0..31
    const int h    = blockIdx.y;
    const int b    = blockIdx.z;
    const int base = qt * 64;
    const int tid  = threadIdx.x;
    const int lane = tid & 31;
    const int warp = tid >> 5;

    // row offset of position p (head h, batch b) in [b, n, h, d] layout
    #define ROWOFF(p) ((size_t)((b * SEQ + (p)) * HEADS + h) * HD)

    // stage q tile
    for (int idx = tid; idx < 64 * 64; idx += 256) {
        int r = idx >> 6, d = idx & 63;
        sq[r * 64 + d] = q[ROWOFF(base + r) + d];
    }
    // stage k/v window: rows j=0..127 -> key = base-64+j (zero-fill below 0)
    for (int idx = tid; idx < 128 * 64; idx += 256) {
        int r = idx >> 6, d = idx & 63;
        int key = base - 64 + r;
        float kv = 0.f, vv = 0.f;
        if (key >= 0) {
            kv = k[ROWOFF(key) + d];
            vv = v[ROWOFF(key) + d];
        }
        sk[r * 65 + d] = kv;
        sv[r * 64 + d] = vv;
    }
    __syncthreads();

    for (int i = warp; i < 64; i += 8) {
        const int qpos = base + i;
        const float* qi = sq + i * 64;

        // ---- local scores: window offsets t = lane, lane+32, 64 ----
        float acc0 = 0.f, acc1 = 0.f, acc2 = 0.f;
        const float* k0 = sk + (i + lane) * 65;
        const float* k1 = sk + (i + lane + 32) * 65;
        const float* k2 = sk + (i + 64) * 65;   // t=64 (key = qpos), uniform across lanes
        #pragma unroll
        for (int d = 0; d < 64; d++) {
            float qd = qi[d];
            acc0 = fmaf(qd, k0[d], acc0);
            acc1 = fmaf(qd, k1[d], acc1);
            acc2 = fmaf(qd, k2[d], acc2);
        }

        // ---- strided score: m = lane + 2, key = qpos - 64m ----
        const int m = lane + 2;
        const bool sval = (m <= qt);
        float acc3 = 0.f;
        if (sval) {
            const float* kr = k + ROWOFF(qpos - 64 * m);
            #pragma unroll
            for (int d4 = 0; d4 < 64; d4 += 4) {
                float4 k4 = *(const float4*)(kr + d4);
                acc3 = fmaf(qi[d4 + 0], k4.x, acc3);
                acc3 = fmaf(qi[d4 + 1], k4.y, acc3);
                acc3 = fmaf(qi[d4 + 2], k4.z, acc3);
                acc3 = fmaf(qi[d4 + 3], k4.w, acc3);
            }
        }

        // validity: key = qpos - 64 + t >= 0  =>  t >= 64 - qpos
        const int tmin = 64 - qpos;
        const bool v0 = (lane >= tmin);
        const bool v1 = (lane + 32 >= tmin);
        // t=64 always valid (key = qpos)

        float mx = fmaxf(fmaxf(v0 ? acc0 : NEGINF, v1 ? acc1 : NEGINF),
                         fmaxf(acc2, sval ? acc3 : NEGINF));
        #pragma unroll
        for (int o = 16; o; o >>= 1) mx = fmaxf(mx, __shfl_xor_sync(0xffffffffu, mx, o));

        float p0 = v0 ? __expf(acc0 - mx) : 0.f;
        float p1 = v1 ? __expf(acc1 - mx) : 0.f;
        float p2 = __expf(acc2 - mx);               // uniform; counted once (lane 0)
        float p3 = sval ? __expf(acc3 - mx) : 0.f;

        float ssum = p0 + p1 + p3 + (lane == 0 ? p2 : 0.f);
        #pragma unroll
        for (int o = 16; o; o >>= 1) ssum += __shfl_xor_sync(0xffffffffu, ssum, o);
        const float inv = 1.f / ssum;

        // ---- weighted V accumulation: lane owns dims (lane, lane+32) ----
        float o0 = 0.f, o1 = 0.f;
        #pragma unroll
        for (int t = 0; t < 32; t++) {
            float wt = __shfl_sync(0xffffffffu, p0, t);
            if (wt != 0.f) {                         // uniform branch
                const float* vr = sv + (i + t) * 64;
                o0 = fmaf(wt, vr[lane], o0);
                o1 = fmaf(wt, vr[lane + 32], o1);
            }
        }
        #pragma unroll
        for (int t = 0; t < 32; t++) {
            float wt = __shfl_sync(0xffffffffu, p1, t);
            if (wt != 0.f) {
                const float* vr = sv + (i + t + 32) * 64;
                o0 = fmaf(wt, vr[lane], o0);
                o1 = fmaf(wt, vr[lane + 32], o1);
            }
        }
        {   // t = 64 (key = qpos)
            const float* vr = sv + (i + 64) * 64;
            o0 = fmaf(p2, vr[lane], o0);
            o1 = fmaf(p2, vr[lane + 32], o1);
        }
        for (int t = 0; t <= qt - 2; t++) {          // strided: m = t+2
            float wt = __shfl_sync(0xffffffffu, p3, t);
            if (wt != 0.f) {
                const float* vr = v + ROWOFF(qpos - 64 * (t + 2));
                o0 = fmaf(wt, vr[lane], o0);
                o1 = fmaf(wt, vr[lane + 32], o1);
            }
        }

        float* orow = out + ROWOFF(qpos);
        orow[lane]      = o0 * inv;
        orow[lane + 32] = o1 * inv;
    }
    #undef ROWOFF
}

// ---------------------------------------------------------------------------
extern "C" void kernel_launch(void* const* d_in, const int* in_sizes, int n_in,
                              void* d_out, int out_size)
{
    const float* x  = (const float*)d_in[0];
    const float* wk = (const float*)d_in[1];
    const float* wq = (const float*)d_in[2];
    const float* wv = (const float*)d_in[3];
    const float* wu = (const float*)d_in[4];
    const float* bu = (const float*)d_in[5];
    float* out = (float*)d_out;

    float *gq, *gk, *gv, *ga;
    cudaGetSymbolAddress((void**)&gq, g_q);
    cudaGetSymbolAddress((void**)&gk, g_k);
    cudaGetSymbolAddress((void**)&gv, g_v);
    cudaGetSymbolAddress((void**)&ga, g_att);

    const float scale = 0.125f;  // 64^-0.5, applied to both q and k (matches ref)

    dim3 gg(HH / 128, MROWS / 128);   // (4, 64)
    gemm128<<<gg, 256>>>(x, wq, gq, MROWS, HH, EMB, scale, nullptr);
    gemm128<<<gg, 256>>>(x, wk, gk, MROWS, HH, EMB, scale, nullptr);
    gemm128<<<gg, 256>>>(x, wv, gv, MROWS, HH, EMB, 1.0f, nullptr);

    cudaFuncSetAttribute(attn_kernel, cudaFuncAttributeMaxDynamicSharedMemorySize,
                         ATTN_SMEM);
    attn_kernel<<<dim3(SEQ / 64, HEADS, BSZ), 256, ATTN_SMEM>>>(gq, gk, gv, ga);

    dim3 gu(EMB / 128, MROWS / 128);  // (4, 64)
    gemm128<<<gu, 256>>>(ga, wu, out, MROWS, EMB, HH, 1.0f, bu);
}

// round 6
// speedup vs baseline: 1.1355x; 1.1355x over previous
#include <cuda_runtime.h>
#include <math.h>

#define BSZ 4
#define SEQ 2048
#define EMB 512
#define HEADS 8
#define HD 64
#define HH 512
#define MROWS (BSZ*SEQ)   // 8192
#define NEGINF (-1e30f)

// Scratch (device globals — no allocation allowed)
__device__ float g_q[MROWS*HH];
__device__ float g_k[MROWS*HH];
__device__ float g_v[MROWS*HH];
__device__ float g_att[MROWS*HH];

// ---------------------------------------------------------------------------
// fp32 tiled GEMM: C[M,Nn] = alpha * A[M,K] @ B[K,Nn] (+ bias[n])
// ---------------------------------------------------------------------------
__global__ void __launch_bounds__(256) gemm128(
    const float* __restrict__ A, const float* __restrict__ B,
    float* __restrict__ C, int M, int Nn, int K,
    float alpha, const float* __restrict__ bias)
{
    __shared__ float As[8][128];
    __shared__ float Bs[8][128];

    const int tid = threadIdx.x;
    const int tx = tid & 15;
    const int ty = tid >> 4;
    const int rm = blockIdx.y * 128;
    const int cn = blockIdx.x * 128;

    const int ar  = tid >> 1;
    const int ac4 = (tid & 1) * 4;
    const int br  = tid >> 5;
    const int bc4 = (tid & 31) * 4;

    const float* Aptr = A + (size_t)(rm + ar) * K + ac4;
    const float* Bptr = B + (size_t)br * Nn + cn + bc4;

    float acc[8][8];
    #pragma unroll
    for (int i = 0; i < 8; i++)
        #pragma unroll
        for (int j = 0; j < 8; j++) acc[i][j] = 0.f;

    for (int kk = 0; kk < K; kk += 8) {
        float4 av = *(const float4*)(Aptr + kk);
        float4 bv = *(const float4*)(Bptr + (size_t)kk * Nn);
        As[ac4 + 0][ar] = av.x;
        As[ac4 + 1][ar] = av.y;
        As[ac4 + 2][ar] = av.z;
        As[ac4 + 3][ar] = av.w;
        *(float4*)&Bs[br][bc4] = bv;
        __syncthreads();

        #pragma unroll
        for (int k = 0; k < 8; k++) {
            float a[8], b[8];
            *(float4*)&a[0] = *(const float4*)&As[k][ty * 8];
            *(float4*)&a[4] = *(const float4*)&As[k][ty * 8 + 4];
            *(float4*)&b[0] = *(const float4*)&Bs[k][tx * 8];
            *(float4*)&b[4] = *(const float4*)&Bs[k][tx * 8 + 4];
            #pragma unroll
            for (int i = 0; i < 8; i++)
                #pragma unroll
                for (int j = 0; j < 8; j++)
                    acc[i][j] = fmaf(a[i], b[j], acc[i][j]);
        }
        __syncthreads();
    }

    #pragma unroll
    for (int i = 0; i < 8; i++) {
        const int row = rm + ty * 8 + i;
        #pragma unroll
        for (int j = 0; j < 8; j += 4) {
            const int col = cn + tx * 8 + j;
            float4 o;
            o.x = acc[i][j + 0] * alpha;
            o.y = acc[i][j + 1] * alpha;
            o.z = acc[i][j + 2] * alpha;
            o.w = acc[i][j + 3] * alpha;
            if (bias) {
                o.x += bias[col + 0];
                o.y += bias[col + 1];
                o.z += bias[col + 2];
                o.w += bias[col + 3];
            }
            *(float4*)(C + (size_t)row * Nn + col) = o;
        }
    }
}

// ---------------------------------------------------------------------------
// GEMM-ified sparse masked attention.
// Block = (64-query tile qt, head h, batch b), 256 threads.
// Phase 1: local scores  S[64 q][128 t] = Qtile @ Kwindow^T   (register GEMM)
//          strided scores S3[q][m] = dot(Q[q], K[q-64m]), m=2..31 (L2 gathers)
// Phase 2: row softmax in registers (shfl over 16-lane groups)
// Phase 3: O = P @ Vwindow (register GEMM) + strided V gathers; scale by 1/sum
// Q/K staging region is unioned with the transposed-prob tile Ps.
// ---------------------------------------------------------------------------
// smem floats: Vs 128*68=8704 | A=max(Qs 64*68 + Ks 64*132, Ps 128*65)=12800
//              | Sstr 64*32=2048 | Sinv 64   -> 23616 floats = 94464 B
#define ATTN_SMEM (23616 * 4)

__global__ void __launch_bounds__(256) attn_kernel(
    const float* __restrict__ q, const float* __restrict__ k,
    const float* __restrict__ v, float* __restrict__ out)
{
    extern __shared__ float sm[];
    float* Vs   = sm;                    // [128][68]
    float* A    = sm + 128 * 68;         // union region
    float* Qs   = A;                     // [64][68]   (transposed: [d][i])
    float* Ks   = A + 64 * 68;           // [64][132]  (transposed: [d][t])
    float* Ps   = A;                     // [128][65]  (transposed: [t][i])
    float* Sstr = sm + 128 * 68 + 12800; // [64][32]
    float* Sinv = Sstr + 64 * 32;        // [64]

    const int qt   = blockIdx.x;
    const int h    = blockIdx.y;
    const int b    = blockIdx.z;
    const int base = qt * 64;
    const int tid  = threadIdx.x;
    const int tx   = tid & 15;
    const int ty   = tid >> 4;

    #define ROWOFF(p) ((size_t)((b * SEQ + (p)) * HEADS + h) * HD)

    // ---- stage Q (transposed) ----
    for (int idx = tid; idx < 64 * 16; idx += 256) {
        int i = idx >> 4, d4 = (idx & 15) * 4;
        float4 t4 = *(const float4*)(q + ROWOFF(base + i) + d4);
        Qs[(d4 + 0) * 68 + i] = t4.x;
        Qs[(d4 + 1) * 68 + i] = t4.y;
        Qs[(d4 + 2) * 68 + i] = t4.z;
        Qs[(d4 + 3) * 68 + i] = t4.w;
    }
    // ---- stage K (transposed) + V (natural) window: t -> key base-64+t ----
    for (int idx = tid; idx < 128 * 16; idx += 256) {
        int t = idx >> 4, d4 = (idx & 15) * 4;
        int key = base - 64 + t;
        float4 kv = make_float4(0.f, 0.f, 0.f, 0.f);
        float4 vv = make_float4(0.f, 0.f, 0.f, 0.f);
        if (key >= 0) {
            kv = *(const float4*)(k + ROWOFF(key) + d4);
            vv = *(const float4*)(v + ROWOFF(key) + d4);
        }
        Ks[(d4 + 0) * 132 + t] = kv.x;
        Ks[(d4 + 1) * 132 + t] = kv.y;
        Ks[(d4 + 2) * 132 + t] = kv.z;
        Ks[(d4 + 3) * 132 + t] = kv.w;
        *(float4*)(Vs + t * 68 + d4) = vv;
    }
    __syncthreads();

    // ---- phase 1a: local score GEMM. thread owns rows ty*4+r, cols tx*8+c ----
    float s[4][8];
    #pragma unroll
    for (int r = 0; r < 4; r++)
        #pragma unroll
        for (int c = 0; c < 8; c++) s[r][c] = 0.f;

    #pragma unroll 4
    for (int kk = 0; kk < 64; kk++) {
        float a0 = Qs[kk * 68 + ty * 4 + 0];
        float a1 = Qs[kk * 68 + ty * 4 + 1];
        float a2 = Qs[kk * 68 + ty * 4 + 2];
        float a3 = Qs[kk * 68 + ty * 4 + 3];
        float4 b0 = *(const float4*)(Ks + kk * 132 + tx * 8);
        float4 b1 = *(const float4*)(Ks + kk * 132 + tx * 8 + 4);
        float bb[8] = {b0.x, b0.y, b0.z, b0.w, b1.x, b1.y, b1.z, b1.w};
        #pragma unroll
        for (int c = 0; c < 8; c++) {
            s[0][c] = fmaf(a0, bb[c], s[0][c]);
            s[1][c] = fmaf(a1, bb[c], s[1][c]);
            s[2][c] = fmaf(a2, bb[c], s[2][c]);
            s[3][c] = fmaf(a3, bb[c], s[3][c]);
        }
    }

    // ---- phase 1b: strided scores. thread -> (query i, m residue) ----
    {
        int i = tid >> 2, sub = tid & 3;
        const float* qcol = Qs + i;
        #pragma unroll
        for (int jj = 0; jj < 8; jj++) {
            int m = 2 + sub + 4 * jj;
            float sv = NEGINF;
            if (m <= qt) {
                const float4* kr = (const float4*)(k + ROWOFF(base + i - 64 * m));
                float acc = 0.f;
                #pragma unroll
                for (int d4 = 0; d4 < 16; d4++) {
                    float4 k4 = kr[d4];
                    acc = fmaf(qcol[(4 * d4 + 0) * 68], k4.x, acc);
                    acc = fmaf(qcol[(4 * d4 + 1) * 68], k4.y, acc);
                    acc = fmaf(qcol[(4 * d4 + 2) * 68], k4.z, acc);
                    acc = fmaf(qcol[(4 * d4 + 3) * 68], k4.w, acc);
                }
                sv = acc;
            }
            Sstr[i * 32 + (m - 2)] = sv;
        }
    }
    __syncthreads();

    // ---- phase 2: softmax per row (16-lane shfl groups; lanes share bit4=ty&1)
    #pragma unroll
    for (int r = 0; r < 4; r++) {
        int i = ty * 4 + r;
        int tlo = (base == 0) ? 64 : i;       // key >= 0 and diff in [0,64]
        if (i > tlo) tlo = i;
        int thi = i + 64;
        float mx = NEGINF;
        #pragma unroll
        for (int c = 0; c < 8; c++) {
            int t = tx * 8 + c;
            if (t < tlo || t > thi) s[r][c] = NEGINF;
            mx = fmaxf(mx, s[r][c]);
        }
        float sv0 = Sstr[i * 32 + tx];
        float sv1 = Sstr[i * 32 + tx + 16];
        mx = fmaxf(mx, fmaxf(sv0, sv1));
        #pragma unroll
        for (int o = 8; o; o >>= 1) mx = fmaxf(mx, __shfl_xor_sync(0xffffffffu, mx, o));

        float sum = 0.f;
        float pl[8];
        #pragma unroll
        for (int c = 0; c < 8; c++) {
            pl[c] = __expf(s[r][c] - mx);
            sum += pl[c];
        }
        float p0 = __expf(sv0 - mx);
        float p1 = __expf(sv1 - mx);
        sum += p0 + p1;
        #pragma unroll
        for (int o = 8; o; o >>= 1) sum += __shfl_xor_sync(0xffffffffu, sum, o);

        // write unnormalized probs (Ps overwrites Qs/Ks — all reads done pre-sync)
        #pragma unroll
        for (int c = 0; c < 8; c++) Ps[(tx * 8 + c) * 65 + i] = pl[c];
        Sstr[i * 32 + tx]      = p0;
        Sstr[i * 32 + tx + 16] = p1;
        if (tx == 0) Sinv[i] = 1.f / sum;
    }
    __syncthreads();

    // ---- phase 3: PV GEMM. thread owns rows ty*4+r, cols tx*4+c ----
    float o[4][4];
    #pragma unroll
    for (int r = 0; r < 4; r++)
        #pragma unroll
        for (int c = 0; c < 4; c++) o[r][c] = 0.f;

    #pragma unroll 4
    for (int kk = 0; kk < 128; kk++) {
        float a0 = Ps[kk * 65 + ty * 4 + 0];
        float a1 = Ps[kk * 65 + ty * 4 + 1];
        float a2 = Ps[kk * 65 + ty * 4 + 2];
        float a3 = Ps[kk * 65 + ty * 4 + 3];
        float4 bb = *(const float4*)(Vs + kk * 68 + tx * 4);
        o[0][0] = fmaf(a0, bb.x, o[0][0]); o[0][1] = fmaf(a0, bb.y, o[0][1]);
        o[0][2] = fmaf(a0, bb.z, o[0][2]); o[0][3] = fmaf(a0, bb.w, o[0][3]);
        o[1][0] = fmaf(a1, bb.x, o[1][0]); o[1][1] = fmaf(a1, bb.y, o[1][1]);
        o[1][2] = fmaf(a1, bb.z, o[1][2]); o[1][3] = fmaf(a1, bb.w, o[1][3]);
        o[2][0] = fmaf(a2, bb.x, o[2][0]); o[2][1] = fmaf(a2, bb.y, o[2][1]);
        o[2][2] = fmaf(a2, bb.z, o[2][2]); o[2][3] = fmaf(a2, bb.w, o[2][3]);
        o[3][0] = fmaf(a3, bb.x, o[3][0]); o[3][1] = fmaf(a3, bb.y, o[3][1]);
        o[3][2] = fmaf(a3, bb.z, o[3][2]); o[3][3] = fmaf(a3, bb.w, o[3][3]);
    }

    // strided PV: gathered V rows (L2-resident)
    for (int j = 0; j + 2 <= qt; j++) {
        #pragma unroll
        for (int r = 0; r < 4; r++) {
            int i = ty * 4 + r;
            float p = Sstr[i * 32 + j];
            float4 vv = *(const float4*)(v + ROWOFF(base + i - 64 * (j + 2)) + tx * 4);
            o[r][0] = fmaf(p, vv.x, o[r][0]);
            o[r][1] = fmaf(p, vv.y, o[r][1]);
            o[r][2] = fmaf(p, vv.z, o[r][2]);
            o[r][3] = fmaf(p, vv.w, o[r][3]);
        }
    }

    #pragma unroll
    for (int r = 0; r < 4; r++) {
        int i = ty * 4 + r;
        float inv = Sinv[i];
        float4 w = make_float4(o[r][0] * inv, o[r][1] * inv,
                               o[r][2] * inv, o[r][3] * inv);
        *(float4*)(out + ROWOFF(base + i) + tx * 4) = w;
    }
    #undef ROWOFF
}

// ---------------------------------------------------------------------------
extern "C" void kernel_launch(void* const* d_in, const int* in_sizes, int n_in,
                              void* d_out, int out_size)
{
    const float* x  = (const float*)d_in[0];
    const float* wk = (const float*)d_in[1];
    const float* wq = (const float*)d_in[2];
    const float* wv = (const float*)d_in[3];
    const float* wu = (const float*)d_in[4];
    const float* bu = (const float*)d_in[5];
    float* out = (float*)d_out;

    float *gq, *gk, *gv, *ga;
    cudaGetSymbolAddress((void**)&gq, g_q);
    cudaGetSymbolAddress((void**)&gk, g_k);
    cudaGetSymbolAddress((void**)&gv, g_v);
    cudaGetSymbolAddress((void**)&ga, g_att);

    const float scale = 0.125f;  // 64^-0.5, applied to both q and k (matches ref)

    dim3 gg(HH / 128, MROWS / 128);
    gemm128<<<gg, 256>>>(x, wq, gq, MROWS, HH, EMB, scale, nullptr);
    gemm128<<<gg, 256>>>(x, wk, gk, MROWS, HH, EMB, scale, nullptr);
    gemm128<<<gg, 256>>>(x, wv, gv, MROWS, HH, EMB, 1.0f, nullptr);

    cudaFuncSetAttribute(attn_kernel, cudaFuncAttributeMaxDynamicSharedMemorySize,
                         ATTN_SMEM);
    attn_kernel<<<dim3(SEQ / 64, HEADS, BSZ), 256, ATTN_SMEM>>>(gq, gk, gv, ga);

    dim3 gu(EMB / 128, MROWS / 128);
    gemm128<<<gu, 256>>>(ga, wu, out, MROWS, EMB, HH, 1.0f, bu);
}

// round 10
// speedup vs baseline: 1.8478x; 1.6273x over previous
#include <cuda_runtime.h>
#include <cuda_bf16.h>
#include <cstdint>
#include <math.h>

#define BSZ 4
#define SEQ 2048
#define EMB 512
#define HEADS 8
#define HD 64
#define HH 512
#define MROWS (BSZ*SEQ)   // 8192
#define NEGINF (-1e30f)

// ---------------------------------------------------------------------------
// Scratch (device globals — no allocation allowed)
// ---------------------------------------------------------------------------
__device__ float g_q[MROWS*HH];
__device__ float g_k[MROWS*HH];
__device__ float g_v[MROWS*HH];
__device__ float g_att[MROWS*HH];
__device__ __nv_bfloat16 g_xh[MROWS*EMB];
__device__ __nv_bfloat16 g_xl[MROWS*EMB];
__device__ __nv_bfloat16 g_ah[MROWS*HH];
__device__ __nv_bfloat16 g_al[MROWS*HH];
__device__ __nv_bfloat16 g_wth[4*EMB*HH];   // [wq,wk,wv,wu] transposed [N][K] hi
__device__ __nv_bfloat16 g_wtl[4*EMB*HH];   // lo

// ---------------------------------------------------------------------------
// Helpers (base-ISA only: ldmatrix / mma.sync / cp.async — no 'a' features)
// ---------------------------------------------------------------------------
__device__ __forceinline__ uint32_t smem_u32(const void* p) {
    uint32_t a;
    asm("{ .reg .u64 t; cvta.to.shared.u64 t, %1; cvt.u32.u64 %0, t; }"
        : "=r"(a) : "l"(p));
    return a;
}

#define LDSM4(r, addr) \
    asm volatile("ldmatrix.sync.aligned.m8n8.x4.shared.b16 {%0,%1,%2,%3}, [%4];" \
        : "=r"((r)[0]), "=r"((r)[1]), "=r"((r)[2]), "=r"((r)[3]) \
        : "r"(addr))

__device__ __forceinline__ void mma_bf16(float* d, const uint32_t* a,
                                         uint32_t b0, uint32_t b1) {
    asm volatile(
        "mma.sync.aligned.m16n8k16.row.col.f32.bf16.bf16.f32 "
        "{%0,%1,%2,%3}, {%4,%5,%6,%7}, {%8,%9}, {%0,%1,%2,%3};"
        : "+f"(d[0]), "+f"(d[1]), "+f"(d[2]), "+f"(d[3])
        : "r"(a[0]), "r"(a[1]), "r"(a[2]), "r"(a[3]), "r"(b0), "r"(b1));
}

#define CP_ASYNC16(dst, src) \
    asm volatile("cp.async.cg.shared.global [%0], [%1], 16;" \
                 :: "r"(dst), "l"(src))
#define CP_COMMIT() asm volatile("cp.async.commit_group;")

// ---------------------------------------------------------------------------
// bf16 split conversion: fp32 -> (hi, lo) bf16
// ---------------------------------------------------------------------------
__global__ void __launch_bounds__(256) split_bf16_k(
    const float* __restrict__ in, __nv_bfloat16* __restrict__ hi,
    __nv_bfloat16* __restrict__ lo, int n)
{
    int i = (blockIdx.x * 256 + threadIdx.x) * 4;
    if (i >= n) return;
    float4 v = *(const float4*)(in + i);
    __nv_bfloat16 h[4], l[4];
    float vv[4] = {v.x, v.y, v.z, v.w};
    #pragma unroll
    for (int j = 0; j < 4; j++) {
        h[j] = __float2bfloat16(vv[j]);
        l[j] = __float2bfloat16(vv[j] - __bfloat162float(h[j]));
    }
    *(uint2*)(hi + i) = *(uint2*)h;
    *(uint2*)(lo + i) = *(uint2*)l;
}

// ---------------------------------------------------------------------------
// Weight transpose + split: W[K=512][N=512] fp32 -> WT_hi/lo [N][K] bf16
// ---------------------------------------------------------------------------
__global__ void __launch_bounds__(256) wsplit_t(
    const float* __restrict__ w0, const float* __restrict__ w1,
    const float* __restrict__ w2, const float* __restrict__ w3,
    __nv_bfloat16* __restrict__ th, __nv_bfloat16* __restrict__ tl)
{
    __shared__ float t[32][33];
    int z = blockIdx.z;
    const float* W = (z == 0) ? w0 : (z == 1) ? w1 : (z == 2) ? w2 : w3;
    __nv_bfloat16* dh = th + (size_t)z * 512 * 512;
    __nv_bfloat16* dl = tl + (size_t)z * 512 * 512;
    int n0 = blockIdx.x * 32, k0 = blockIdx.y * 32;
    int tx = threadIdx.x & 31, ty = threadIdx.x >> 5;
    #pragma unroll
    for (int i = 0; i < 4; i++) {
        int r = ty + i * 8;
        t[r][tx] = W[(size_t)(k0 + r) * 512 + n0 + tx];
    }
    __syncthreads();
    #pragma unroll
    for (int i = 0; i < 4; i++) {
        int r = ty + i * 8;
        float x = t[tx][r];
        __nv_bfloat16 h = __float2bfloat16(x);
        __nv_bfloat16 l = __float2bfloat16(x - __bfloat162float(h));
        dh[(size_t)(n0 + r) * 512 + k0 + tx] = h;
        dl[(size_t)(n0 + r) * 512 + k0 + tx] = l;
    }
}

// ---------------------------------------------------------------------------
// mma.sync split-precision GEMM tile: C[128 m][128 n] = alpha*(A@B^T) (+bias)
// A (Ah,Al): [8192][512] bf16 row-major. B (Bh,Bl): [512 n][512 k] bf16.
// Accumulates Ah@Bh + Ah@Bl + Al@Bh in fp32 registers.
// SMEM: double-buffered K=32 chunks, 4 buffers (Ah|Al|Bh|Bl), 128 rows,
// row stride 40 bf16 (80 B) -> conflict-free ldmatrix.
// ---------------------------------------------------------------------------
#define BUF_B   10240              // 128 * 80
#define STG_B   (4 * BUF_B)        // 40960
#define MMA_SMEM (2 * STG_B)       // 81920

__device__ __forceinline__ void stage_load(
    uint32_t sdst,
    const __nv_bfloat16* a0, const __nv_bfloat16* a1,
    const __nv_bfloat16* b0, const __nv_bfloat16* b1, int tid)
{
    const __nv_bfloat16* srcs[4] = {a0, a1, b0, b1};
    #pragma unroll
    for (int b = 0; b < 4; ++b) {
        uint32_t dst = sdst + b * BUF_B;
        #pragma unroll
        for (int it = 0; it < 2; ++it) {
            int idx = tid + it * 256;
            int r = idx >> 2, seg = idx & 3;
            CP_ASYNC16(dst + r * 80 + seg * 16,
                       __cvta_generic_to_global(srcs[b] + (size_t)r * 512 + seg * 8));
        }
    }
}

__device__ __forceinline__ void mma_gemm_128x128(
    const __nv_bfloat16* __restrict__ Ah, const __nv_bfloat16* __restrict__ Al,
    const __nv_bfloat16* __restrict__ Bh, const __nv_bfloat16* __restrict__ Bl,
    float* __restrict__ C, float alpha, const float* __restrict__ bias,
    int m0, int n0)
{
    extern __shared__ __align__(16) uint8_t smem[];
    const uint32_t sbase = smem_u32(smem);
    const int tid  = threadIdx.x;
    const int lane = tid & 31, wid = tid >> 5;
    const int wm = wid >> 1, wn = wid & 1;

    const __nv_bfloat16* pAh = Ah + (size_t)m0 * 512;
    const __nv_bfloat16* pAl = Al + (size_t)m0 * 512;
    const __nv_bfloat16* pBh = Bh + (size_t)n0 * 512;
    const __nv_bfloat16* pBl = Bl + (size_t)n0 * 512;

    float acc[2][8][4];
    #pragma unroll
    for (int mf = 0; mf < 2; mf++)
        #pragma unroll
        for (int nf = 0; nf < 8; nf++)
            #pragma unroll
            for (int j = 0; j < 4; j++) acc[mf][nf][j] = 0.f;

    // ldmatrix per-lane address offsets (within a buffer)
    const uint32_t aoff =
        (uint32_t)(wm * 32 + (lane & 15)) * 80 + (lane >> 4) * 16;
    const uint32_t boff =
        (uint32_t)(wn * 64 + (lane & 7) + ((lane >> 3) & 1) * 8) * 80
        + (lane >> 4) * 16;

    stage_load(sbase, pAh, pAl, pBh, pBl, tid);
    CP_COMMIT();

    for (int c = 0; c < 16; ++c) {                 // K chunks of 32
        if (c < 15) {
            stage_load(sbase + ((c + 1) & 1) * STG_B,
                       pAh + (c + 1) * 32, pAl + (c + 1) * 32,
                       pBh + (c + 1) * 32, pBl + (c + 1) * 32, tid);
            CP_COMMIT();
            asm volatile("cp.async.wait_group 1;");
        } else {
            asm volatile("cp.async.wait_group 0;");
        }
        __syncthreads();

        const uint32_t st = sbase + (c & 1) * STG_B;
        #pragma unroll
        for (int t = 0; t < 2; ++t) {              // k16 steps
            const uint32_t ka = t * 32;
            uint32_t a_h[2][4], a_l[2][4], bb[4][4];

            LDSM4(a_h[0], st + aoff + ka);
            LDSM4(a_h[1], st + aoff + 16 * 80 + ka);
            #pragma unroll
            for (int g = 0; g < 4; ++g)
                LDSM4(bb[g], st + 2 * BUF_B + boff + g * 16 * 80 + ka);

            // P1: Ah @ Bh
            #pragma unroll
            for (int mf = 0; mf < 2; ++mf)
                #pragma unroll
                for (int nf = 0; nf < 8; ++nf)
                    mma_bf16(acc[mf][nf], a_h[mf],
                             bb[nf >> 1][nf & 1], bb[nf >> 1][2 + (nf & 1)]);

            // P3: Al @ Bh (Bh frags still live)
            LDSM4(a_l[0], st + BUF_B + aoff + ka);
            LDSM4(a_l[1], st + BUF_B + aoff + 16 * 80 + ka);
            #pragma unroll
            for (int mf = 0; mf < 2; ++mf)
                #pragma unroll
                for (int nf = 0; nf < 8; ++nf)
                    mma_bf16(acc[mf][nf], a_l[mf],
                             bb[nf >> 1][nf & 1], bb[nf >> 1][2 + (nf & 1)]);

            // P2: Ah @ Bl (reuse bb regs)
            #pragma unroll
            for (int g = 0; g < 4; ++g)
                LDSM4(bb[g], st + 3 * BUF_B + boff + g * 16 * 80 + ka);
            #pragma unroll
            for (int mf = 0; mf < 2; ++mf)
                #pragma unroll
                for (int nf = 0; nf < 8; ++nf)
                    mma_bf16(acc[mf][nf], a_h[mf],
                             bb[nf >> 1][nf & 1], bb[nf >> 1][2 + (nf & 1)]);
        }
        __syncthreads();
    }

    // epilogue: direct frag stores
    #pragma unroll
    for (int mf = 0; mf < 2; ++mf) {
        const int r0 = m0 + wm * 32 + mf * 16 + (lane >> 2);
        #pragma unroll
        for (int nf = 0; nf < 8; ++nf) {
            const int col = n0 + wn * 64 + nf * 8 + (lane & 3) * 2;
            float bx = 0.f, by = 0.f;
            if (bias) { bx = bias[col]; by = bias[col + 1]; }
            float2 v0 = make_float2(acc[mf][nf][0] * alpha + bx,
                                    acc[mf][nf][1] * alpha + by);
            float2 v1 = make_float2(acc[mf][nf][2] * alpha + bx,
                                    acc[mf][nf][3] * alpha + by);
            *(float2*)(C + (size_t)r0 * 512 + col) = v0;
            *(float2*)(C + (size_t)(r0 + 8) * 512 + col) = v1;
        }
    }
}

// Fused Q/K/V projection: z picks weight + destination (+ qk scale)
__global__ void __launch_bounds__(256) proj_mma(
    const __nv_bfloat16* __restrict__ xh, const __nv_bfloat16* __restrict__ xl,
    const __nv_bfloat16* __restrict__ wth, const __nv_bfloat16* __restrict__ wtl,
    float* __restrict__ gq, float* __restrict__ gk, float* __restrict__ gv)
{
    int z = blockIdx.z;
    const __nv_bfloat16* bh = wth + (size_t)z * 512 * 512;
    const __nv_bfloat16* bl = wtl + (size_t)z * 512 * 512;
    float* C = (z == 0) ? gq : (z == 1) ? gk : gv;
    float alpha = (z == 2) ? 1.0f : 0.125f;      // 64^-0.5 on q and k
    mma_gemm_128x128(xh, xl, bh, bl, C, alpha, nullptr,
                     blockIdx.y * 128, blockIdx.x * 128);
}

__global__ void __launch_bounds__(256) unify_mma(
    const __nv_bfloat16* __restrict__ ah, const __nv_bfloat16* __restrict__ al,
    const __nv_bfloat16* __restrict__ wth, const __nv_bfloat16* __restrict__ wtl,
    float* __restrict__ out, const float* __restrict__ bias)
{
    mma_gemm_128x128(ah, al, wth + 3ull * 512 * 512, wtl + 3ull * 512 * 512,
                     out, 1.0f, bias, blockIdx.y * 128, blockIdx.x * 128);
}

// ---------------------------------------------------------------------------
// GEMM-ified sparse masked attention (unchanged from R6 — 177us, passes).
// ---------------------------------------------------------------------------
#define ATTN_SMEM (23616 * 4)

__global__ void __launch_bounds__(256) attn_kernel(
    const float* __restrict__ q, const float* __restrict__ k,
    const float* __restrict__ v, float* __restrict__ out)
{
    extern __shared__ float sm[];
    float* Vs   = sm;                    // [128][68]
    float* A    = sm + 128 * 68;         // union region
    float* Qs   = A;                     // [64][68]   (transposed: [d][i])
    float* Ks   = A + 64 * 68;           // [64][132]  (transposed: [d][t])
    float* Ps   = A;                     // [128][65]  (transposed: [t][i])
    float* Sstr = sm + 128 * 68 + 12800; // [64][32]
    float* Sinv = Sstr + 64 * 32;        // [64]

    const int qt   = blockIdx.x;
    const int h    = blockIdx.y;
    const int b    = blockIdx.z;
    const int base = qt * 64;
    const int tid  = threadIdx.x;
    const int tx   = tid & 15;
    const int ty   = tid >> 4;

    #define ROWOFF(p) ((size_t)((b * SEQ + (p)) * HEADS + h) * HD)

    for (int idx = tid; idx < 64 * 16; idx += 256) {
        int i = idx >> 4, d4 = (idx & 15) * 4;
        float4 t4 = *(const float4*)(q + ROWOFF(base + i) + d4);
        Qs[(d4 + 0) * 68 + i] = t4.x;
        Qs[(d4 + 1) * 68 + i] = t4.y;
        Qs[(d4 + 2) * 68 + i] = t4.z;
        Qs[(d4 + 3) * 68 + i] = t4.w;
    }
    for (int idx = tid; idx < 128 * 16; idx += 256) {
        int t = idx >> 4, d4 = (idx & 15) * 4;
        int key = base - 64 + t;
        float4 kv = make_float4(0.f, 0.f, 0.f, 0.f);
        float4 vv = make_float4(0.f, 0.f, 0.f, 0.f);
        if (key >= 0) {
            kv = *(const float4*)(k + ROWOFF(key) + d4);
            vv = *(const float4*)(v + ROWOFF(key) + d4);
        }
        Ks[(d4 + 0) * 132 + t] = kv.x;
        Ks[(d4 + 1) * 132 + t] = kv.y;
        Ks[(d4 + 2) * 132 + t] = kv.z;
        Ks[(d4 + 3) * 132 + t] = kv.w;
        *(float4*)(Vs + t * 68 + d4) = vv;
    }
    __syncthreads();

    float s[4][8];
    #pragma unroll
    for (int r = 0; r < 4; r++)
        #pragma unroll
        for (int c = 0; c < 8; c++) s[r][c] = 0.f;

    #pragma unroll 4
    for (int kk = 0; kk < 64; kk++) {
        float a0 = Qs[kk * 68 + ty * 4 + 0];
        float a1 = Qs[kk * 68 + ty * 4 + 1];
        float a2 = Qs[kk * 68 + ty * 4 + 2];
        float a3 = Qs[kk * 68 + ty * 4 + 3];
        float4 b0 = *(const float4*)(Ks + kk * 132 + tx * 8);
        float4 b1 = *(const float4*)(Ks + kk * 132 + tx * 8 + 4);
        float bb[8] = {b0.x, b0.y, b0.z, b0.w, b1.x, b1.y, b1.z, b1.w};
        #pragma unroll
        for (int c = 0; c < 8; c++) {
            s[0][c] = fmaf(a0, bb[c], s[0][c]);
            s[1][c] = fmaf(a1, bb[c], s[1][c]);
            s[2][c] = fmaf(a2, bb[c], s[2][c]);
            s[3][c] = fmaf(a3, bb[c], s[3][c]);
        }
    }

    {
        int i = tid >> 2, sub = tid & 3;
        const float* qcol = Qs + i;
        #pragma unroll
        for (int jj = 0; jj < 8; jj++) {
            int m = 2 + sub + 4 * jj;
            float sv = NEGINF;
            if (m <= qt) {
                const float4* kr = (const float4*)(k + ROWOFF(base + i - 64 * m));
                float acc = 0.f;
                #pragma unroll
                for (int d4 = 0; d4 < 16; d4++) {
                    float4 k4 = kr[d4];
                    acc = fmaf(qcol[(4 * d4 + 0) * 68], k4.x, acc);
                    acc = fmaf(qcol[(4 * d4 + 1) * 68], k4.y, acc);
                    acc = fmaf(qcol[(4 * d4 + 2) * 68], k4.z, acc);
                    acc = fmaf(qcol[(4 * d4 + 3) * 68], k4.w, acc);
                }
                sv = acc;
            }
            Sstr[i * 32 + (m - 2)] = sv;
        }
    }
    __syncthreads();

    #pragma unroll
    for (int r = 0; r < 4; r++) {
        int i = ty * 4 + r;
        int tlo = (base == 0) ? 64 : i;
        if (i > tlo) tlo = i;
        int thi = i + 64;
        float mx = NEGINF;
        #pragma unroll
        for (int c = 0; c < 8; c++) {
            int t = tx * 8 + c;
            if (t < tlo || t > thi) s[r][c] = NEGINF;
            mx = fmaxf(mx, s[r][c]);
        }
        float sv0 = Sstr[i * 32 + tx];
        float sv1 = Sstr[i * 32 + tx + 16];
        mx = fmaxf(mx, fmaxf(sv0, sv1));
        #pragma unroll
        for (int o = 8; o; o >>= 1) mx = fmaxf(mx, __shfl_xor_sync(0xffffffffu, mx, o));

        float sum = 0.f;
        float pl[8];
        #pragma unroll
        for (int c = 0; c < 8; c++) {
            pl[c] = __expf(s[r][c] - mx);
            sum += pl[c];
        }
        float p0 = __expf(sv0 - mx);
        float p1 = __expf(sv1 - mx);
        sum += p0 + p1;
        #pragma unroll
        for (int o = 8; o; o >>= 1) sum += __shfl_xor_sync(0xffffffffu, sum, o);

        #pragma unroll
        for (int c = 0; c < 8; c++) Ps[(tx * 8 + c) * 65 + i] = pl[c];
        Sstr[i * 32 + tx]      = p0;
        Sstr[i * 32 + tx + 16] = p1;
        if (tx == 0) Sinv[i] = 1.f / sum;
    }
    __syncthreads();

    float o[4][4];
    #pragma unroll
    for (int r = 0; r < 4; r++)
        #pragma unroll
        for (int c = 0; c < 4; c++) o[r][c] = 0.f;

    #pragma unroll 4
    for (int kk = 0; kk < 128; kk++) {
        float a0 = Ps[kk * 65 + ty * 4 + 0];
        float a1 = Ps[kk * 65 + ty * 4 + 1];
        float a2 = Ps[kk * 65 + ty * 4 + 2];
        float a3 = Ps[kk * 65 + ty * 4 + 3];
        float4 bb = *(const float4*)(Vs + kk * 68 + tx * 4);
        o[0][0] = fmaf(a0, bb.x, o[0][0]); o[0][1] = fmaf(a0, bb.y, o[0][1]);
        o[0][2] = fmaf(a0, bb.z, o[0][2]); o[0][3] = fmaf(a0, bb.w, o[0][3]);
        o[1][0] = fmaf(a1, bb.x, o[1][0]); o[1][1] = fmaf(a1, bb.y, o[1][1]);
        o[1][2] = fmaf(a1, bb.z, o[1][2]); o[1][3] = fmaf(a1, bb.w, o[1][3]);
        o[2][0] = fmaf(a2, bb.x, o[2][0]); o[2][1] = fmaf(a2, bb.y, o[2][1]);
        o[2][2] = fmaf(a2, bb.z, o[2][2]); o[2][3] = fmaf(a2, bb.w, o[2][3]);
        o[3][0] = fmaf(a3, bb.x, o[3][0]); o[3][1] = fmaf(a3, bb.y, o[3][1]);
        o[3][2] = fmaf(a3, bb.z, o[3][2]); o[3][3] = fmaf(a3, bb.w, o[3][3]);
    }

    for (int j = 0; j + 2 <= qt; j++) {
        #pragma unroll
        for (int r = 0; r < 4; r++) {
            int i = ty * 4 + r;
            float p = Sstr[i * 32 + j];
            float4 vv = *(const float4*)(v + ROWOFF(base + i - 64 * (j + 2)) + tx * 4);
            o[r][0] = fmaf(p, vv.x, o[r][0]);
            o[r][1] = fmaf(p, vv.y, o[r][1]);
            o[r][2] = fmaf(p, vv.z, o[r][2]);
            o[r][3] = fmaf(p, vv.w, o[r][3]);
        }
    }

    #pragma unroll
    for (int r = 0; r < 4; r++) {
        int i = ty * 4 + r;
        float inv = Sinv[i];
        float4 w = make_float4(o[r][0] * inv, o[r][1] * inv,
                               o[r][2] * inv, o[r][3] * inv);
        *(float4*)(out + ROWOFF(base + i) + tx * 4) = w;
    }
    #undef ROWOFF
}

// ---------------------------------------------------------------------------
extern "C" void kernel_launch(void* const* d_in, const int* in_sizes, int n_in,
                              void* d_out, int out_size)
{
    const float* x  = (const float*)d_in[0];
    const float* wk = (const float*)d_in[1];
    const float* wq = (const float*)d_in[2];
    const float* wv = (const float*)d_in[3];
    const float* wu = (const float*)d_in[4];
    const float* bu = (const float*)d_in[5];
    float* out = (float*)d_out;

    float *gq, *gk, *gv, *ga;
    __nv_bfloat16 *xh, *xl, *ah, *al, *wth, *wtl;
    cudaGetSymbolAddress((void**)&gq,  g_q);
    cudaGetSymbolAddress((void**)&gk,  g_k);
    cudaGetSymbolAddress((void**)&gv,  g_v);
    cudaGetSymbolAddress((void**)&ga,  g_att);
    cudaGetSymbolAddress((void**)&xh,  g_xh);
    cudaGetSymbolAddress((void**)&xl,  g_xl);
    cudaGetSymbolAddress((void**)&ah,  g_ah);
    cudaGetSymbolAddress((void**)&al,  g_al);
    cudaGetSymbolAddress((void**)&wth, g_wth);
    cudaGetSymbolAddress((void**)&wtl, g_wtl);

    // 1) split x into bf16 hi/lo; transpose+split weights [wq,wk,wv,wu]
    split_bf16_k<<<(MROWS * EMB) / 1024, 256>>>(x, xh, xl, MROWS * EMB);
    wsplit_t<<<dim3(16, 16, 4), 256>>>(wq, wk, wv, wu, wth, wtl);

    // 2) fused HMMA Q/K/V projections
    cudaFuncSetAttribute(proj_mma, cudaFuncAttributeMaxDynamicSharedMemorySize,
                         MMA_SMEM);
    proj_mma<<<dim3(HH / 128, MROWS / 128, 3), 256, MMA_SMEM>>>(
        xh, xl, wth, wtl, gq, gk, gv);

    // 3) sparse attention
    cudaFuncSetAttribute(attn_kernel, cudaFuncAttributeMaxDynamicSharedMemorySize,
                         ATTN_SMEM);
    attn_kernel<<<dim3(SEQ / 64, HEADS, BSZ), 256, ATTN_SMEM>>>(gq, gk, gv, ga);

    // 4) split attention output, HMMA unify projection (+bias)
    split_bf16_k<<<(MROWS * HH) / 1024, 256>>>(ga, ah, al, MROWS * HH);
    cudaFuncSetAttribute(unify_mma, cudaFuncAttributeMaxDynamicSharedMemorySize,
                         MMA_SMEM);
    unify_mma<<<dim3(EMB / 128, MROWS / 128), 256, MMA_SMEM>>>(
        ah, al, wth, wtl, out, bu);
}

// round 11
// speedup vs baseline: 2.1126x; 1.1433x over previous
#include <cuda_runtime.h>
#include <cuda_bf16.h>
#include <cstdint>
#include <math.h>

#define BSZ 4
#define SEQ 2048
#define EMB 512
#define HEADS 8
#define HD 64
#define HH 512
#define MROWS (BSZ*SEQ)   // 8192
#define NEGINF (-1e30f)

// ---------------------------------------------------------------------------
// Scratch (device globals — no allocation allowed)
// ---------------------------------------------------------------------------
__device__ float g_q[MROWS*HH];
__device__ float g_k[MROWS*HH];
__device__ float g_v[MROWS*HH];
__device__ __nv_bfloat16 g_qh[MROWS*HH];
__device__ __nv_bfloat16 g_ql[MROWS*HH];
__device__ __nv_bfloat16 g_kh[MROWS*HH];
__device__ __nv_bfloat16 g_kl[MROWS*HH];
__device__ __nv_bfloat16 g_vh[MROWS*HH];
__device__ __nv_bfloat16 g_vl[MROWS*HH];
__device__ __nv_bfloat16 g_xh[MROWS*EMB];
__device__ __nv_bfloat16 g_xl[MROWS*EMB];
__device__ __nv_bfloat16 g_ah[MROWS*HH];
__device__ __nv_bfloat16 g_al[MROWS*HH];
__device__ __nv_bfloat16 g_wth[4*EMB*HH];   // [wq,wk,wv,wu] transposed [N][K] hi
__device__ __nv_bfloat16 g_wtl[4*EMB*HH];   // lo

// ---------------------------------------------------------------------------
// Helpers (base-ISA only: ldmatrix / mma.sync / cp.async)
// ---------------------------------------------------------------------------
__device__ __forceinline__ uint32_t smem_u32(const void* p) {
    uint32_t a;
    asm("{ .reg .u64 t; cvta.to.shared.u64 t, %1; cvt.u32.u64 %0, t; }"
        : "=r"(a) : "l"(p));
    return a;
}

#define LDSM4(r, addr) \
    asm volatile("ldmatrix.sync.aligned.m8n8.x4.shared.b16 {%0,%1,%2,%3}, [%4];" \
        : "=r"((r)[0]), "=r"((r)[1]), "=r"((r)[2]), "=r"((r)[3]) \
        : "r"(addr))

#define LDSM4T(r, addr) \
    asm volatile("ldmatrix.sync.aligned.m8n8.x4.trans.shared.b16 {%0,%1,%2,%3}, [%4];" \
        : "=r"((r)[0]), "=r"((r)[1]), "=r"((r)[2]), "=r"((r)[3]) \
        : "r"(addr))

__device__ __forceinline__ void mma_bf16(float* d, const uint32_t* a,
                                         uint32_t b0, uint32_t b1) {
    asm volatile(
        "mma.sync.aligned.m16n8k16.row.col.f32.bf16.bf16.f32 "
        "{%0,%1,%2,%3}, {%4,%5,%6,%7}, {%8,%9}, {%0,%1,%2,%3};"
        : "+f"(d[0]), "+f"(d[1]), "+f"(d[2]), "+f"(d[3])
        : "r"(a[0]), "r"(a[1]), "r"(a[2]), "r"(a[3]), "r"(b0), "r"(b1));
}

#define CP_ASYNC16(dst, src) \
    asm volatile("cp.async.cg.shared.global [%0], [%1], 16;" \
                 :: "r"(dst), "l"(src))
#define CP_COMMIT() asm volatile("cp.async.commit_group;")

// ---------------------------------------------------------------------------
// bf16 split conversion: fp32 -> (hi, lo) bf16   (used for x only)
// ---------------------------------------------------------------------------
__global__ void __launch_bounds__(256) split_bf16_k(
    const float* __restrict__ in, __nv_bfloat16* __restrict__ hi,
    __nv_bfloat16* __restrict__ lo, int n)
{
    int i = (blockIdx.x * 256 + threadIdx.x) * 4;
    if (i >= n) return;
    float4 v = *(const float4*)(in + i);
    __nv_bfloat16 h[4], l[4];
    float vv[4] = {v.x, v.y, v.z, v.w};
    #pragma unroll
    for (int j = 0; j < 4; j++) {
        h[j] = __float2bfloat16(vv[j]);
        l[j] = __float2bfloat16(vv[j] - __bfloat162float(h[j]));
    }
    *(uint2*)(hi + i) = *(uint2*)h;
    *(uint2*)(lo + i) = *(uint2*)l;
}

// ---------------------------------------------------------------------------
// Weight transpose + split
// ---------------------------------------------------------------------------
__global__ void __launch_bounds__(256) wsplit_t(
    const float* __restrict__ w0, const float* __restrict__ w1,
    const float* __restrict__ w2, const float* __restrict__ w3,
    __nv_bfloat16* __restrict__ th, __nv_bfloat16* __restrict__ tl)
{
    __shared__ float t[32][33];
    int z = blockIdx.z;
    const float* W = (z == 0) ? w0 : (z == 1) ? w1 : (z == 2) ? w2 : w3;
    __nv_bfloat16* dh = th + (size_t)z * 512 * 512;
    __nv_bfloat16* dl = tl + (size_t)z * 512 * 512;
    int n0 = blockIdx.x * 32, k0 = blockIdx.y * 32;
    int tx = threadIdx.x & 31, ty = threadIdx.x >> 5;
    #pragma unroll
    for (int i = 0; i < 4; i++) {
        int r = ty + i * 8;
        t[r][tx] = W[(size_t)(k0 + r) * 512 + n0 + tx];
    }
    __syncthreads();
    #pragma unroll
    for (int i = 0; i < 4; i++) {
        int r = ty + i * 8;
        float x = t[tx][r];
        __nv_bfloat16 h = __float2bfloat16(x);
        __nv_bfloat16 l = __float2bfloat16(x - __bfloat162float(h));
        dh[(size_t)(n0 + r) * 512 + k0 + tx] = h;
        dl[(size_t)(n0 + r) * 512 + k0 + tx] = l;
    }
}

// ---------------------------------------------------------------------------
// mma.sync split-precision GEMM tile (as R10), optionally emitting bf16 hi/lo
// of the result alongside the fp32 output.
// ---------------------------------------------------------------------------
#define BUF_B   10240              // 128 * 80
#define STG_B   (4 * BUF_B)
#define MMA_SMEM (2 * STG_B)       // 81920

__device__ __forceinline__ void stage_load(
    uint32_t sdst,
    const __nv_bfloat16* a0, const __nv_bfloat16* a1,
    const __nv_bfloat16* b0, const __nv_bfloat16* b1, int tid)
{
    const __nv_bfloat16* srcs[4] = {a0, a1, b0, b1};
    #pragma unroll
    for (int b = 0; b < 4; ++b) {
        uint32_t dst = sdst + b * BUF_B;
        #pragma unroll
        for (int it = 0; it < 2; ++it) {
            int idx = tid + it * 256;
            int r = idx >> 2, seg = idx & 3;
            CP_ASYNC16(dst + r * 80 + seg * 16,
                       __cvta_generic_to_global(srcs[b] + (size_t)r * 512 + seg * 8));
        }
    }
}

__device__ __forceinline__ void mma_gemm_128x128(
    const __nv_bfloat16* __restrict__ Ah, const __nv_bfloat16* __restrict__ Al,
    const __nv_bfloat16* __restrict__ Bh, const __nv_bfloat16* __restrict__ Bl,
    float* __restrict__ C, float alpha, const float* __restrict__ bias,
    int m0, int n0,
    __nv_bfloat16* __restrict__ Ch, __nv_bfloat16* __restrict__ Cl)
{
    extern __shared__ __align__(16) uint8_t smem[];
    const uint32_t sbase = smem_u32(smem);
    const int tid  = threadIdx.x;
    const int lane = tid & 31, wid = tid >> 5;
    const int wm = wid >> 1, wn = wid & 1;

    const __nv_bfloat16* pAh = Ah + (size_t)m0 * 512;
    const __nv_bfloat16* pAl = Al + (size_t)m0 * 512;
    const __nv_bfloat16* pBh = Bh + (size_t)n0 * 512;
    const __nv_bfloat16* pBl = Bl + (size_t)n0 * 512;

    float acc[2][8][4];
    #pragma unroll
    for (int mf = 0; mf < 2; mf++)
        #pragma unroll
        for (int nf = 0; nf < 8; nf++)
            #pragma unroll
            for (int j = 0; j < 4; j++) acc[mf][nf][j] = 0.f;

    const uint32_t aoff =
        (uint32_t)(wm * 32 + (lane & 15)) * 80 + (lane >> 4) * 16;
    const uint32_t boff =
        (uint32_t)(wn * 64 + (lane & 7) + ((lane >> 3) & 1) * 8) * 80
        + (lane >> 4) * 16;

    stage_load(sbase, pAh, pAl, pBh, pBl, tid);
    CP_COMMIT();

    for (int c = 0; c < 16; ++c) {
        if (c < 15) {
            stage_load(sbase + ((c + 1) & 1) * STG_B,
                       pAh + (c + 1) * 32, pAl + (c + 1) * 32,
                       pBh + (c + 1) * 32, pBl + (c + 1) * 32, tid);
            CP_COMMIT();
            asm volatile("cp.async.wait_group 1;");
        } else {
            asm volatile("cp.async.wait_group 0;");
        }
        __syncthreads();

        const uint32_t st = sbase + (c & 1) * STG_B;
        #pragma unroll
        for (int t = 0; t < 2; ++t) {
            const uint32_t ka = t * 32;
            uint32_t a_h[2][4], a_l[2][4], bb[4][4];

            LDSM4(a_h[0], st + aoff + ka);
            LDSM4(a_h[1], st + aoff + 16 * 80 + ka);
            #pragma unroll
            for (int g = 0; g < 4; ++g)
                LDSM4(bb[g], st + 2 * BUF_B + boff + g * 16 * 80 + ka);

            #pragma unroll
            for (int mf = 0; mf < 2; ++mf)
                #pragma unroll
                for (int nf = 0; nf < 8; ++nf)
                    mma_bf16(acc[mf][nf], a_h[mf],
                             bb[nf >> 1][nf & 1], bb[nf >> 1][2 + (nf & 1)]);

            LDSM4(a_l[0], st + BUF_B + aoff + ka);
            LDSM4(a_l[1], st + BUF_B + aoff + 16 * 80 + ka);
            #pragma unroll
            for (int mf = 0; mf < 2; ++mf)
                #pragma unroll
                for (int nf = 0; nf < 8; ++nf)
                    mma_bf16(acc[mf][nf], a_l[mf],
                             bb[nf >> 1][nf & 1], bb[nf >> 1][2 + (nf & 1)]);

            #pragma unroll
            for (int g = 0; g < 4; ++g)
                LDSM4(bb[g], st + 3 * BUF_B + boff + g * 16 * 80 + ka);
            #pragma unroll
            for (int mf = 0; mf < 2; ++mf)
                #pragma unroll
                for (int nf = 0; nf < 8; ++nf)
                    mma_bf16(acc[mf][nf], a_h[mf],
                             bb[nf >> 1][nf & 1], bb[nf >> 1][2 + (nf & 1)]);
        }
        __syncthreads();
    }

    #pragma unroll
    for (int mf = 0; mf < 2; ++mf) {
        const int r0 = m0 + wm * 32 + mf * 16 + (lane >> 2);
        #pragma unroll
        for (int nf = 0; nf < 8; ++nf) {
            const int col = n0 + wn * 64 + nf * 8 + (lane & 3) * 2;
            float bx = 0.f, by = 0.f;
            if (bias) { bx = bias[col]; by = bias[col + 1]; }
            float2 v0 = make_float2(acc[mf][nf][0] * alpha + bx,
                                    acc[mf][nf][1] * alpha + by);
            float2 v1 = make_float2(acc[mf][nf][2] * alpha + bx,
                                    acc[mf][nf][3] * alpha + by);
            *(float2*)(C + (size_t)r0 * 512 + col) = v0;
            *(float2*)(C + (size_t)(r0 + 8) * 512 + col) = v1;
            if (Ch) {
                __nv_bfloat162 hh, ll;
                hh.x = __float2bfloat16(v0.x);
                hh.y = __float2bfloat16(v0.y);
                ll.x = __float2bfloat16(v0.x - __bfloat162float(hh.x));
                ll.y = __float2bfloat16(v0.y - __bfloat162float(hh.y));
                *(__nv_bfloat162*)(Ch + (size_t)r0 * 512 + col) = hh;
                *(__nv_bfloat162*)(Cl + (size_t)r0 * 512 + col) = ll;
                hh.x = __float2bfloat16(v1.x);
                hh.y = __float2bfloat16(v1.y);
                ll.x = __float2bfloat16(v1.x - __bfloat162float(hh.x));
                ll.y = __float2bfloat16(v1.y - __bfloat162float(hh.y));
                *(__nv_bfloat162*)(Ch + (size_t)(r0 + 8) * 512 + col) = hh;
                *(__nv_bfloat162*)(Cl + (size_t)(r0 + 8) * 512 + col) = ll;
            }
        }
    }
}

__global__ void __launch_bounds__(256) proj_mma(
    const __nv_bfloat16* __restrict__ xh, const __nv_bfloat16* __restrict__ xl,
    const __nv_bfloat16* __restrict__ wth, const __nv_bfloat16* __restrict__ wtl,
    float* gq, float* gk, float* gv,
    __nv_bfloat16* qh, __nv_bfloat16* ql,
    __nv_bfloat16* kh, __nv_bfloat16* kl,
    __nv_bfloat16* vh, __nv_bfloat16* vl)
{
    int z = blockIdx.z;
    const __nv_bfloat16* bh = wth + (size_t)z * 512 * 512;
    const __nv_bfloat16* bl = wtl + (size_t)z * 512 * 512;
    float* C = (z == 0) ? gq : (z == 1) ? gk : gv;
    __nv_bfloat16* Ch = (z == 0) ? qh : (z == 1) ? kh : vh;
    __nv_bfloat16* Cl = (z == 0) ? ql : (z == 1) ? kl : vl;
    float alpha = (z == 2) ? 1.0f : 0.125f;
    mma_gemm_128x128(xh, xl, bh, bl, C, alpha, nullptr,
                     blockIdx.y * 128, blockIdx.x * 128, Ch, Cl);
}

__global__ void __launch_bounds__(256) unify_mma(
    const __nv_bfloat16* __restrict__ ah, const __nv_bfloat16* __restrict__ al,
    const __nv_bfloat16* __restrict__ wth, const __nv_bfloat16* __restrict__ wtl,
    float* __restrict__ out, const float* __restrict__ bias)
{
    mma_gemm_128x128(ah, al, wth + 3ull * 512 * 512, wtl + 3ull * 512 * 512,
                     out, 1.0f, bias, blockIdx.y * 128, blockIdx.x * 128,
                     nullptr, nullptr);
}

// ---------------------------------------------------------------------------
// HMMA sparse attention.
// Block = (64-query tile, head, batch), 256 threads = 8 warps (2m x 4n).
// S = Q @ Kwin^T via mma.sync (split bf16, 3 passes); strided scores SIMT
// (overlapped with cp.async staging); softmax on fragments; P stored bf16 h/l
// over the K region; O = P @ Vwin via mma.sync (V frags via ldmatrix.trans);
// strided PV SIMT in epilogue. Output written directly as bf16 hi/lo (unify in).
// ---------------------------------------------------------------------------
#define SM_QH      0         // 64 x 72 bf16 (stride 144B)
#define SM_QL      9216
#define SM_KH      18432     // 128 x 72 bf16 | later Ph 64 x 136 bf16 (272B)
#define SM_KL      36864     // 128 x 72 bf16 | later Pl
#define SM_VH      55296     // 128 x 72 bf16
#define SM_VL      73728
#define SM_SSTR    92160     // fp32 [64][32]
#define SM_REDMAX  100352    // fp32 [64][4]
#define SM_REDSUM  101376    // fp32 [64][4]
#define SM_SMAX    102400    // fp32 [64]
#define SM_SSUMSTR 102656    // fp32 [64]
#define ATTN_SMEM  102912

__global__ void __launch_bounds__(256, 2) attn_kernel(
    const float* __restrict__ qf, const float* __restrict__ kf,
    const float* __restrict__ vf,
    const __nv_bfloat16* __restrict__ qh, const __nv_bfloat16* __restrict__ ql,
    const __nv_bfloat16* __restrict__ kh, const __nv_bfloat16* __restrict__ kl,
    const __nv_bfloat16* __restrict__ vh, const __nv_bfloat16* __restrict__ vl,
    __nv_bfloat16* __restrict__ oh, __nv_bfloat16* __restrict__ ol)
{
    extern __shared__ __align__(16) char smraw[];
    const uint32_t sb = smem_u32(smraw);
    const int qt   = blockIdx.x;
    const int h    = blockIdx.y;
    const int b    = blockIdx.z;
    const int base = qt * 64;
    const int tid  = threadIdx.x;
    const int lane = tid & 31, wid = tid >> 5;
    const int wm = wid >> 2, wn = wid & 3;

    float* SSTR    = (float*)(smraw + SM_SSTR);
    float* REDMAX  = (float*)(smraw + SM_REDMAX);
    float* REDSUM  = (float*)(smraw + SM_REDSUM);
    float* SMAXA   = (float*)(smraw + SM_SMAX);
    float* SSUMSTR = (float*)(smraw + SM_SSUMSTR);

    #define ROWOFF(p) ((size_t)((b * SEQ + (p)) * HEADS + h) * HD)

    // ---- stage Q (hi/lo): 2 x 64 rows x 8 segs ----
    for (int idx = tid; idx < 1024; idx += 256) {
        int buf = idx >> 9, rem = idx & 511;
        int i = rem >> 3, seg = rem & 7;
        const __nv_bfloat16* src = (buf ? ql : qh) + ROWOFF(base + i) + seg * 8;
        CP_ASYNC16(sb + SM_QH + buf * 9216 + i * 144 + seg * 16,
                   __cvta_generic_to_global(src));
    }
    // ---- stage K/V window (hi/lo): 4 x 128 rows x 8 segs ----
    for (int idx = tid; idx < 4096; idx += 256) {
        int buf = idx >> 10, rem = idx & 1023;
        int t = rem >> 3, seg = rem & 7;
        int key = base - 64 + t;
        uint32_t dstoff = (buf == 0 ? SM_KH : buf == 1 ? SM_KL :
                           buf == 2 ? SM_VH : SM_VL) + t * 144 + seg * 16;
        if (key >= 0) {
            const __nv_bfloat16* src =
                (buf == 0 ? kh : buf == 1 ? kl : buf == 2 ? vh : vl)
                + ROWOFF(key) + seg * 8;
            CP_ASYNC16(sb + dstoff, __cvta_generic_to_global(src));
        } else {
            *(uint4*)(smraw + dstoff) = make_uint4(0, 0, 0, 0);
        }
    }
    CP_COMMIT();

    // ---- strided scores (fp32, from global; overlaps cp.async) ----
    const int si = tid >> 2, sub = tid & 3;
    {
        const float* qr = qf + ROWOFF(base + si) + sub * 16;
        float4 q0 = *(const float4*)(qr + 0);
        float4 q1 = *(const float4*)(qr + 4);
        float4 q2 = *(const float4*)(qr + 8);
        float4 q3 = *(const float4*)(qr + 12);
        float mx = NEGINF;
        for (int m = 2; m <= qt; m++) {
            const float* kr = kf + ROWOFF(base + si - 64 * m) + sub * 16;
            float4 k0 = *(const float4*)(kr + 0);
            float4 k1 = *(const float4*)(kr + 4);
            float4 k2 = *(const float4*)(kr + 8);
            float4 k3 = *(const float4*)(kr + 12);
            float a = q0.x*k0.x + q0.y*k0.y + q0.z*k0.z + q0.w*k0.w
                    + q1.x*k1.x + q1.y*k1.y + q1.z*k1.z + q1.w*k1.w
                    + q2.x*k2.x + q2.y*k2.y + q2.z*k2.z + q2.w*k2.w
                    + q3.x*k3.x + q3.y*k3.y + q3.z*k3.z + q3.w*k3.w;
            a += __shfl_xor_sync(0xffffffffu, a, 1);
            a += __shfl_xor_sync(0xffffffffu, a, 2);
            if (sub == 0) { SSTR[si * 32 + m - 2] = a; mx = fmaxf(mx, a); }
        }
        if (sub == 0) SMAXA[si] = mx;
    }

    asm volatile("cp.async.wait_group 0;");
    __syncthreads();   // B0: staged tiles + strided scores visible

    // ---- S = Q @ Kwin^T (HMMA, 3 split passes) ----
    float accs[2][4][4];
    #pragma unroll
    for (int mf = 0; mf < 2; mf++)
        #pragma unroll
        for (int nf = 0; nf < 4; nf++)
            #pragma unroll
            for (int j = 0; j < 4; j++) accs[mf][nf][j] = 0.f;

    const uint32_t aQrow = (uint32_t)(wm * 32 + (lane & 15)) * 144
                         + (lane >> 4) * 16;
    const uint32_t bKrow = (uint32_t)(wn * 32 + (lane & 7)
                         + ((lane >> 3) & 1) * 8) * 144 + (lane >> 4) * 16;

    #pragma unroll
    for (int kd = 0; kd < 4; kd++) {
        const uint32_t ka = kd * 32;
        uint32_t a_h[2][4], a_l[2][4], bh4[2][4], bl4[2][4];
        LDSM4(a_h[0], sb + SM_QH + aQrow + ka);
        LDSM4(a_h[1], sb + SM_QH + aQrow + 16 * 144 + ka);
        LDSM4(a_l[0], sb + SM_QL + aQrow + ka);
        LDSM4(a_l[1], sb + SM_QL + aQrow + 16 * 144 + ka);
        #pragma unroll
        for (int g = 0; g < 2; g++) {
            LDSM4(bh4[g], sb + SM_KH + bKrow + g * 16 * 144 + ka);
            LDSM4(bl4[g], sb + SM_KL + bKrow + g * 16 * 144 + ka);
        }
        #pragma unroll
        for (int mf = 0; mf < 2; mf++)
            #pragma unroll
            for (int nf = 0; nf < 4; nf++) {
                mma_bf16(accs[mf][nf], a_h[mf],
                         bh4[nf >> 1][nf & 1], bh4[nf >> 1][2 + (nf & 1)]);
                mma_bf16(accs[mf][nf], a_l[mf],
                         bh4[nf >> 1][nf & 1], bh4[nf >> 1][2 + (nf & 1)]);
                mma_bf16(accs[mf][nf], a_h[mf],
                         bl4[nf >> 1][nf & 1], bl4[nf >> 1][2 + (nf & 1)]);
            }
    }

    // ---- mask + per-warp row max ----
    #pragma unroll
    for (int mf = 0; mf < 2; mf++)
        #pragma unroll
        for (int rh = 0; rh < 2; rh++) {
            int q_l = wm * 32 + mf * 16 + rh * 8 + (lane >> 2);
            int tlo = (base == 0) ? 64 : q_l;
            int thi = q_l + 64;
            float m = NEGINF;
            #pragma unroll
            for (int nf = 0; nf < 4; nf++)
                #pragma unroll
                for (int c = 0; c < 2; c++) {
                    int t = wn * 32 + nf * 8 + (lane & 3) * 2 + c;
                    float& sv = accs[mf][nf][rh * 2 + c];
                    if (t < tlo || t > thi) sv = NEGINF;
                    m = fmaxf(m, sv);
                }
            m = fmaxf(m, __shfl_xor_sync(0xffffffffu, m, 1));
            m = fmaxf(m, __shfl_xor_sync(0xffffffffu, m, 2));
            if ((lane & 3) == 0) REDMAX[q_l * 4 + wn] = m;
        }
    __syncthreads();   // B1: K reads done, row maxes visible

    // ---- exp fragments -> P (bf16 hi/lo over K region), row sums ----
    #pragma unroll
    for (int mf = 0; mf < 2; mf++)
        #pragma unroll
        for (int rh = 0; rh < 2; rh++) {
            int q_l = wm * 32 + mf * 16 + rh * 8 + (lane >> 2);
            float Mr = fmaxf(fmaxf(REDMAX[q_l * 4 + 0], REDMAX[q_l * 4 + 1]),
                             fmaxf(REDMAX[q_l * 4 + 2], REDMAX[q_l * 4 + 3]));
            Mr = fmaxf(Mr, SMAXA[q_l]);
            float rsum = 0.f;
            #pragma unroll
            for (int nf = 0; nf < 4; nf++) {
                float p0 = __expf(accs[mf][nf][rh * 2 + 0] - Mr);
                float p1 = __expf(accs[mf][nf][rh * 2 + 1] - Mr);
                rsum += p0 + p1;
                int t0 = wn * 32 + nf * 8 + (lane & 3) * 2;
                uint32_t addr = (uint32_t)q_l * 272 + t0 * 2;
                __nv_bfloat162 hh, ll;
                hh.x = __float2bfloat16(p0);
                hh.y = __float2bfloat16(p1);
                ll.x = __float2bfloat16(p0 - __bfloat162float(hh.x));
                ll.y = __float2bfloat16(p1 - __bfloat162float(hh.y));
                *(__nv_bfloat162*)(smraw + SM_KH + addr) = hh;
                *(__nv_bfloat162*)(smraw + SM_KL + addr) = ll;
            }
            rsum += __shfl_xor_sync(0xffffffffu, rsum, 1);
            rsum += __shfl_xor_sync(0xffffffffu, rsum, 2);
            if ((lane & 3) == 0) REDSUM[q_l * 4 + wn] = rsum;
        }

    // ---- exp strided scores ----
    {
        float Mi = fmaxf(fmaxf(REDMAX[si * 4 + 0], REDMAX[si * 4 + 1]),
                         fmaxf(REDMAX[si * 4 + 2], REDMAX[si * 4 + 3]));
        Mi = fmaxf(Mi, SMAXA[si]);
        float ss = 0.f;
        for (int m = 2 + sub; m <= qt; m += 4) {
            float p = __expf(SSTR[si * 32 + m - 2] - Mi);
            SSTR[si * 32 + m - 2] = p;
            ss += p;
        }
        ss += __shfl_xor_sync(0xffffffffu, ss, 1);
        ss += __shfl_xor_sync(0xffffffffu, ss, 2);
        if (sub == 0) SSUMSTR[si] = ss;
    }
    __syncthreads();   // B2: P, V, sums ready

    // ---- O = P @ Vwin (HMMA, 3 split passes; V frags via ldmatrix.trans) ----
    float acco[2][2][4];
    #pragma unroll
    for (int mf = 0; mf < 2; mf++)
        #pragma unroll
        for (int nf = 0; nf < 2; nf++)
            #pragma unroll
            for (int j = 0; j < 4; j++) acco[mf][nf][j] = 0.f;

    const uint32_t aProw = (uint32_t)(wm * 32 + (lane & 15)) * 272
                         + (lane >> 4) * 16;
    const uint32_t bVcol = (uint32_t)(wn * 16 + (lane >> 4) * 8) * 2;

    #pragma unroll
    for (int kt = 0; kt < 8; kt++) {
        uint32_t pa_h[2][4], pa_l[2][4], vbh[4], vbl[4];
        LDSM4(pa_h[0], sb + SM_KH + aProw + kt * 32);
        LDSM4(pa_h[1], sb + SM_KH + aProw + 16 * 272 + kt * 32);
        LDSM4(pa_l[0], sb + SM_KL + aProw + kt * 32);
        LDSM4(pa_l[1], sb + SM_KL + aProw + 16 * 272 + kt * 32);
        uint32_t vrow = (uint32_t)(kt * 16 + (lane & 15)) * 144 + bVcol;
        LDSM4T(vbh, sb + SM_VH + vrow);
        LDSM4T(vbl, sb + SM_VL + vrow);
        #pragma unroll
        for (int mf = 0; mf < 2; mf++) {
            mma_bf16(acco[mf][0], pa_h[mf], vbh[0], vbh[1]);
            mma_bf16(acco[mf][1], pa_h[mf], vbh[2], vbh[3]);
            mma_bf16(acco[mf][0], pa_h[mf], vbl[0], vbl[1]);
            mma_bf16(acco[mf][1], pa_h[mf], vbl[2], vbl[3]);
            mma_bf16(acco[mf][0], pa_l[mf], vbh[0], vbh[1]);
            mma_bf16(acco[mf][1], pa_l[mf], vbh[2], vbh[3]);
        }
    }

    // ---- epilogue: strided PV (SIMT) + normalize + store bf16 hi/lo ----
    const int d0 = wn * 16 + (lane & 3) * 2;
    #pragma unroll
    for (int mf = 0; mf < 2; mf++)
        #pragma unroll
        for (int rh = 0; rh < 2; rh++) {
            int q_l = wm * 32 + mf * 16 + rh * 8 + (lane >> 2);
            int qpos = base + q_l;
            float o00 = acco[mf][0][rh * 2 + 0];
            float o01 = acco[mf][0][rh * 2 + 1];
            float o10 = acco[mf][1][rh * 2 + 0];
            float o11 = acco[mf][1][rh * 2 + 1];
            for (int j = 0; j + 2 <= qt; j++) {
                float p = SSTR[q_l * 32 + j];
                const float* vr = vf + ROWOFF(qpos - 64 * (j + 2));
                float2 va = *(const float2*)(vr + d0);
                float2 vb = *(const float2*)(vr + d0 + 8);
                o00 += p * va.x; o01 += p * va.y;
                o10 += p * vb.x; o11 += p * vb.y;
            }
            float sum = REDSUM[q_l * 4 + 0] + REDSUM[q_l * 4 + 1]
                      + REDSUM[q_l * 4 + 2] + REDSUM[q_l * 4 + 3]
                      + SSUMSTR[q_l];
            float inv = 1.f / sum;
            o00 *= inv; o01 *= inv; o10 *= inv; o11 *= inv;
            size_t off = ROWOFF(qpos) + d0;
            __nv_bfloat162 hh, ll;
            hh.x = __float2bfloat16(o00);
            hh.y = __float2bfloat16(o01);
            ll.x = __float2bfloat16(o00 - __bfloat162float(hh.x));
            ll.y = __float2bfloat16(o01 - __bfloat162float(hh.y));
            *(__nv_bfloat162*)(oh + off) = hh;
            *(__nv_bfloat162*)(ol + off) = ll;
            hh.x = __float2bfloat16(o10);
            hh.y = __float2bfloat16(o11);
            ll.x = __float2bfloat16(o10 - __bfloat162float(hh.x));
            ll.y = __float2bfloat16(o11 - __bfloat162float(hh.y));
            *(__nv_bfloat162*)(oh + off + 8) = hh;
            *(__nv_bfloat162*)(ol + off + 8) = ll;
        }
    #undef ROWOFF
}

// ---------------------------------------------------------------------------
extern "C" void kernel_launch(void* const* d_in, const int* in_sizes, int n_in,
                              void* d_out, int out_size)
{
    const float* x  = (const float*)d_in[0];
    const float* wk = (const float*)d_in[1];
    const float* wq = (const float*)d_in[2];
    const float* wv = (const float*)d_in[3];
    const float* wu = (const float*)d_in[4];
    const float* bu = (const float*)d_in[5];
    float* out = (float*)d_out;

    float *gq, *gk, *gv;
    __nv_bfloat16 *xh, *xl, *ah, *al, *wth, *wtl;
    __nv_bfloat16 *qh, *ql, *kh, *kl, *vh, *vl;
    cudaGetSymbolAddress((void**)&gq,  g_q);
    cudaGetSymbolAddress((void**)&gk,  g_k);
    cudaGetSymbolAddress((void**)&gv,  g_v);
    cudaGetSymbolAddress((void**)&xh,  g_xh);
    cudaGetSymbolAddress((void**)&xl,  g_xl);
    cudaGetSymbolAddress((void**)&ah,  g_ah);
    cudaGetSymbolAddress((void**)&al,  g_al);
    cudaGetSymbolAddress((void**)&wth, g_wth);
    cudaGetSymbolAddress((void**)&wtl, g_wtl);
    cudaGetSymbolAddress((void**)&qh,  g_qh);
    cudaGetSymbolAddress((void**)&ql,  g_ql);
    cudaGetSymbolAddress((void**)&kh,  g_kh);
    cudaGetSymbolAddress((void**)&kl,  g_kl);
    cudaGetSymbolAddress((void**)&vh,  g_vh);
    cudaGetSymbolAddress((void**)&vl,  g_vl);

    // 1) split x; transpose+split weights
    split_bf16_k<<<(MROWS * EMB) / 1024, 256>>>(x, xh, xl, MROWS * EMB);
    wsplit_t<<<dim3(16, 16, 4), 256>>>(wq, wk, wv, wu, wth, wtl);

    // 2) HMMA Q/K/V projections (emit fp32 + bf16 hi/lo)
    cudaFuncSetAttribute(proj_mma, cudaFuncAttributeMaxDynamicSharedMemorySize,
                         MMA_SMEM);
    proj_mma<<<dim3(HH / 128, MROWS / 128, 3), 256, MMA_SMEM>>>(
        xh, xl, wth, wtl, gq, gk, gv, qh, ql, kh, kl, vh, vl);

    // 3) HMMA sparse attention (writes ah/al directly)
    cudaFuncSetAttribute(attn_kernel, cudaFuncAttributeMaxDynamicSharedMemorySize,
                         ATTN_SMEM);
    attn_kernel<<<dim3(SEQ / 64, HEADS, BSZ), 256, ATTN_SMEM>>>(
        gq, gk, gv, qh, ql, kh, kl, vh, vl, ah, al);

    // 4) HMMA unify projection (+bias)
    cudaFuncSetAttribute(unify_mma, cudaFuncAttributeMaxDynamicSharedMemorySize,
                         MMA_SMEM);
    unify_mma<<<dim3(EMB / 128, MROWS / 128), 256, MMA_SMEM>>>(
        ah, al, wth, wtl, out, bu);
}

// round 13
// speedup vs baseline: 2.6719x; 1.2648x over previous
#include <cuda_runtime.h>
#include <cuda_bf16.h>
#include <cstdint>
#include <math.h>

#define BSZ 4
#define SEQ 2048
#define EMB 512
#define HEADS 8
#define HD 64
#define HH 512
#define MROWS (BSZ*SEQ)   // 8192
#define NEGINF (-1e30f)

// ---------------------------------------------------------------------------
// Scratch (device globals — no allocation allowed)
// ---------------------------------------------------------------------------
__device__ float g_ol[MROWS*HH];            // unnormalized local attention out
__device__ float g_ml[MROWS*HEADS];         // local row max
__device__ float g_sl[MROWS*HEADS];         // local row sum
__device__ __nv_bfloat16 g_qh[MROWS*HH];
__device__ __nv_bfloat16 g_ql[MROWS*HH];
__device__ __nv_bfloat16 g_kh[MROWS*HH];
__device__ __nv_bfloat16 g_kl[MROWS*HH];
__device__ __nv_bfloat16 g_vh[MROWS*HH];
__device__ __nv_bfloat16 g_vl[MROWS*HH];
__device__ __nv_bfloat16 g_xh[MROWS*EMB];
__device__ __nv_bfloat16 g_xl[MROWS*EMB];
__device__ __nv_bfloat16 g_ah[MROWS*HH];
__device__ __nv_bfloat16 g_al[MROWS*HH];
__device__ __nv_bfloat16 g_wth[4*EMB*HH];   // [wq,wk,wv,wu] transposed [N][K] hi
__device__ __nv_bfloat16 g_wtl[4*EMB*HH];   // lo

// ---------------------------------------------------------------------------
// Helpers (base-ISA only: ldmatrix / mma.sync / cp.async)
// ---------------------------------------------------------------------------
__device__ __forceinline__ uint32_t smem_u32(const void* p) {
    uint32_t a;
    asm("{ .reg .u64 t; cvta.to.shared.u64 t, %1; cvt.u32.u64 %0, t; }"
        : "=r"(a) : "l"(p));
    return a;
}

#define LDSM4(r, addr) \
    asm volatile("ldmatrix.sync.aligned.m8n8.x4.shared.b16 {%0,%1,%2,%3}, [%4];" \
        : "=r"((r)[0]), "=r"((r)[1]), "=r"((r)[2]), "=r"((r)[3]) \
        : "r"(addr))

#define LDSM4T(r, addr) \
    asm volatile("ldmatrix.sync.aligned.m8n8.x4.trans.shared.b16 {%0,%1,%2,%3}, [%4];" \
        : "=r"((r)[0]), "=r"((r)[1]), "=r"((r)[2]), "=r"((r)[3]) \
        : "r"(addr))

__device__ __forceinline__ void mma_bf16(float* d, const uint32_t* a,
                                         uint32_t b0, uint32_t b1) {
    asm volatile(
        "mma.sync.aligned.m16n8k16.row.col.f32.bf16.bf16.f32 "
        "{%0,%1,%2,%3}, {%4,%5,%6,%7}, {%8,%9}, {%0,%1,%2,%3};"
        : "+f"(d[0]), "+f"(d[1]), "+f"(d[2]), "+f"(d[3])
        : "r"(a[0]), "r"(a[1]), "r"(a[2]), "r"(a[3]), "r"(b0), "r"(b1));
}

#define CP_ASYNC16(dst, src) \
    asm volatile("cp.async.cg.shared.global [%0], [%1], 16;" \
                 :: "r"(dst), "l"(src))
#define CP_COMMIT() asm volatile("cp.async.commit_group;")

// ---------------------------------------------------------------------------
// bf16 split conversion (x only)
// ---------------------------------------------------------------------------
__global__ void __launch_bounds__(256) split_bf16_k(
    const float* __restrict__ in, __nv_bfloat16* __restrict__ hi,
    __nv_bfloat16* __restrict__ lo, int n)
{
    int i = (blockIdx.x * 256 + threadIdx.x) * 4;
    if (i >= n) return;
    float4 v = *(const float4*)(in + i);
    __nv_bfloat16 h[4], l[4];
    float vv[4] = {v.x, v.y, v.z, v.w};
    #pragma unroll
    for (int j = 0; j < 4; j++) {
        h[j] = __float2bfloat16(vv[j]);
        l[j] = __float2bfloat16(vv[j] - __bfloat162float(h[j]));
    }
    *(uint2*)(hi + i) = *(uint2*)h;
    *(uint2*)(lo + i) = *(uint2*)l;
}

// ---------------------------------------------------------------------------
// Weight transpose + split
// ---------------------------------------------------------------------------
__global__ void __launch_bounds__(256) wsplit_t(
    const float* __restrict__ w0, const float* __restrict__ w1,
    const float* __restrict__ w2, const float* __restrict__ w3,
    __nv_bfloat16* __restrict__ th, __nv_bfloat16* __restrict__ tl)
{
    __shared__ float t[32][33];
    int z = blockIdx.z;
    const float* W = (z == 0) ? w0 : (z == 1) ? w1 : (z == 2) ? w2 : w3;
    __nv_bfloat16* dh = th + (size_t)z * 512 * 512;
    __nv_bfloat16* dl = tl + (size_t)z * 512 * 512;
    int n0 = blockIdx.x * 32, k0 = blockIdx.y * 32;
    int tx = threadIdx.x & 31, ty = threadIdx.x >> 5;
    #pragma unroll
    for (int i = 0; i < 4; i++) {
        int r = ty + i * 8;
        t[r][tx] = W[(size_t)(k0 + r) * 512 + n0 + tx];
    }
    __syncthreads();
    #pragma unroll
    for (int i = 0; i < 4; i++) {
        int r = ty + i * 8;
        float x = t[tx][r];
        __nv_bfloat16 h = __float2bfloat16(x);
        __nv_bfloat16 l = __float2bfloat16(x - __bfloat162float(h));
        dh[(size_t)(n0 + r) * 512 + k0 + tx] = h;
        dl[(size_t)(n0 + r) * 512 + k0 + tx] = l;
    }
}

// ---------------------------------------------------------------------------
// mma.sync split-precision GEMM tile (fp32 C optional; bf16 hi/lo optional)
// ---------------------------------------------------------------------------
#define BUF_B   10240              // 128 * 80
#define STG_B   (4 * BUF_B)
#define MMA_SMEM (2 * STG_B)       // 81920

__device__ __forceinline__ void stage_load(
    uint32_t sdst,
    const __nv_bfloat16* a0, const __nv_bfloat16* a1,
    const __nv_bfloat16* b0, const __nv_bfloat16* b1, int tid)
{
    const __nv_bfloat16* srcs[4] = {a0, a1, b0, b1};
    #pragma unroll
    for (int b = 0; b < 4; ++b) {
        uint32_t dst = sdst + b * BUF_B;
        #pragma unroll
        for (int it = 0; it < 2; ++it) {
            int idx = tid + it * 256;
            int r = idx >> 2, seg = idx & 3;
            CP_ASYNC16(dst + r * 80 + seg * 16,
                       __cvta_generic_to_global(srcs[b] + (size_t)r * 512 + seg * 8));
        }
    }
}

__device__ __forceinline__ void mma_gemm_128x128(
    const __nv_bfloat16* __restrict__ Ah, const __nv_bfloat16* __restrict__ Al,
    const __nv_bfloat16* __restrict__ Bh, const __nv_bfloat16* __restrict__ Bl,
    float* __restrict__ C, float alpha, const float* __restrict__ bias,
    int m0, int n0,
    __nv_bfloat16* __restrict__ Ch, __nv_bfloat16* __restrict__ Cl)
{
    extern __shared__ __align__(16) uint8_t smem[];
    const uint32_t sbase = smem_u32(smem);
    const int tid  = threadIdx.x;
    const int lane = tid & 31, wid = tid >> 5;
    const int wm = wid >> 1, wn = wid & 1;

    const __nv_bfloat16* pAh = Ah + (size_t)m0 * 512;
    const __nv_bfloat16* pAl = Al + (size_t)m0 * 512;
    const __nv_bfloat16* pBh = Bh + (size_t)n0 * 512;
    const __nv_bfloat16* pBl = Bl + (size_t)n0 * 512;

    float acc[2][8][4];
    #pragma unroll
    for (int mf = 0; mf < 2; mf++)
        #pragma unroll
        for (int nf = 0; nf < 8; nf++)
            #pragma unroll
            for (int j = 0; j < 4; j++) acc[mf][nf][j] = 0.f;

    const uint32_t aoff =
        (uint32_t)(wm * 32 + (lane & 15)) * 80 + (lane >> 4) * 16;
    const uint32_t boff =
        (uint32_t)(wn * 64 + (lane & 7) + ((lane >> 3) & 1) * 8) * 80
        + (lane >> 4) * 16;

    stage_load(sbase, pAh, pAl, pBh, pBl, tid);
    CP_COMMIT();

    for (int c = 0; c < 16; ++c) {
        if (c < 15) {
            stage_load(sbase + ((c + 1) & 1) * STG_B,
                       pAh + (c + 1) * 32, pAl + (c + 1) * 32,
                       pBh + (c + 1) * 32, pBl + (c + 1) * 32, tid);
            CP_COMMIT();
            asm volatile("cp.async.wait_group 1;");
        } else {
            asm volatile("cp.async.wait_group 0;");
        }
        __syncthreads();

        const uint32_t st = sbase + (c & 1) * STG_B;
        #pragma unroll
        for (int t = 0; t < 2; ++t) {
            const uint32_t ka = t * 32;
            uint32_t a_h[2][4], a_l[2][4], bb[4][4];

            LDSM4(a_h[0], st + aoff + ka);
            LDSM4(a_h[1], st + aoff + 16 * 80 + ka);
            #pragma unroll
            for (int g = 0; g < 4; ++g)
                LDSM4(bb[g], st + 2 * BUF_B + boff + g * 16 * 80 + ka);

            #pragma unroll
            for (int mf = 0; mf < 2; ++mf)
                #pragma unroll
                for (int nf = 0; nf < 8; ++nf)
                    mma_bf16(acc[mf][nf], a_h[mf],
                             bb[nf >> 1][nf & 1], bb[nf >> 1][2 + (nf & 1)]);

            LDSM4(a_l[0], st + BUF_B + aoff + ka);
            LDSM4(a_l[1], st + BUF_B + aoff + 16 * 80 + ka);
            #pragma unroll
            for (int mf = 0; mf < 2; ++mf)
                #pragma unroll
                for (int nf = 0; nf < 8; ++nf)
                    mma_bf16(acc[mf][nf], a_l[mf],
                             bb[nf >> 1][nf & 1], bb[nf >> 1][2 + (nf & 1)]);

            #pragma unroll
            for (int g = 0; g < 4; ++g)
                LDSM4(bb[g], st + 3 * BUF_B + boff + g * 16 * 80 + ka);
            #pragma unroll
            for (int mf = 0; mf < 2; ++mf)
                #pragma unroll
                for (int nf = 0; nf < 8; ++nf)
                    mma_bf16(acc[mf][nf], a_h[mf],
                             bb[nf >> 1][nf & 1], bb[nf >> 1][2 + (nf & 1)]);
        }
        __syncthreads();
    }

    #pragma unroll
    for (int mf = 0; mf < 2; ++mf) {
        const int r0 = m0 + wm * 32 + mf * 16 + (lane >> 2);
        #pragma unroll
        for (int nf = 0; nf < 8; ++nf) {
            const int col = n0 + wn * 64 + nf * 8 + (lane & 3) * 2;
            float bx = 0.f, by = 0.f;
            if (bias) { bx = bias[col]; by = bias[col + 1]; }
            float2 v0 = make_float2(acc[mf][nf][0] * alpha + bx,
                                    acc[mf][nf][1] * alpha + by);
            float2 v1 = make_float2(acc[mf][nf][2] * alpha + bx,
                                    acc[mf][nf][3] * alpha + by);
            if (C) {
                *(float2*)(C + (size_t)r0 * 512 + col) = v0;
                *(float2*)(C + (size_t)(r0 + 8) * 512 + col) = v1;
            }
            if (Ch) {
                __nv_bfloat162 hh, ll;
                hh.x = __float2bfloat16(v0.x);
                hh.y = __float2bfloat16(v0.y);
                ll.x = __float2bfloat16(v0.x - __bfloat162float(hh.x));
                ll.y = __float2bfloat16(v0.y - __bfloat162float(hh.y));
                *(__nv_bfloat162*)(Ch + (size_t)r0 * 512 + col) = hh;
                *(__nv_bfloat162*)(Cl + (size_t)r0 * 512 + col) = ll;
                hh.x = __float2bfloat16(v1.x);
                hh.y = __float2bfloat16(v1.y);
                ll.x = __float2bfloat16(v1.x - __bfloat162float(hh.x));
                ll.y = __float2bfloat16(v1.y - __bfloat162float(hh.y));
                *(__nv_bfloat162*)(Ch + (size_t)(r0 + 8) * 512 + col) = hh;
                *(__nv_bfloat162*)(Cl + (size_t)(r0 + 8) * 512 + col) = ll;
            }
        }
    }
}

__global__ void __launch_bounds__(256) proj_mma(
    const __nv_bfloat16* __restrict__ xh, const __nv_bfloat16* __restrict__ xl,
    const __nv_bfloat16* __restrict__ wth, const __nv_bfloat16* __restrict__ wtl,
    __nv_bfloat16* qh, __nv_bfloat16* ql,
    __nv_bfloat16* kh, __nv_bfloat16* kl,
    __nv_bfloat16* vh, __nv_bfloat16* vl)
{
    int z = blockIdx.z;
    const __nv_bfloat16* bh = wth + (size_t)z * 512 * 512;
    const __nv_bfloat16* bl = wtl + (size_t)z * 512 * 512;
    __nv_bfloat16* Ch = (z == 0) ? qh : (z == 1) ? kh : vh;
    __nv_bfloat16* Cl = (z == 0) ? ql : (z == 1) ? kl : vl;
    float alpha = (z == 2) ? 1.0f : 0.125f;
    mma_gemm_128x128(xh, xl, bh, bl, nullptr, alpha, nullptr,
                     blockIdx.y * 128, blockIdx.x * 128, Ch, Cl);
}

__global__ void __launch_bounds__(256) unify_mma(
    const __nv_bfloat16* __restrict__ ah, const __nv_bfloat16* __restrict__ al,
    const __nv_bfloat16* __restrict__ wth, const __nv_bfloat16* __restrict__ wtl,
    float* __restrict__ out, const float* __restrict__ bias)
{
    mma_gemm_128x128(ah, al, wth + 3ull * 512 * 512, wtl + 3ull * 512 * 512,
                     out, 1.0f, bias, blockIdx.y * 128, blockIdx.x * 128,
                     nullptr, nullptr);
}

// ---------------------------------------------------------------------------
// Local-window attention (HMMA). Writes UNNORMALIZED O_local (fp32) + per-row
// (max, sum). Strided part handled by attn_strided.
// ---------------------------------------------------------------------------
#define SM_QH      0         // 64 x 72 bf16 (stride 144B)
#define SM_QL      9216
#define SM_KH      18432     // 128 x 72 bf16 | later Ph 64 x 136 bf16 (272B)
#define SM_KL      36864     // 128 x 72 bf16 | later Pl
#define SM_VH      55296     // 128 x 72 bf16
#define SM_VL      73728
#define SM_REDMAX  92160     // fp32 [64][4]
#define SM_REDSUM  93184     // fp32 [64][4]
#define ATTN_SMEM  94208

__global__ void __launch_bounds__(256, 2) attn_local(
    const __nv_bfloat16* __restrict__ qh, const __nv_bfloat16* __restrict__ ql,
    const __nv_bfloat16* __restrict__ kh, const __nv_bfloat16* __restrict__ kl,
    const __nv_bfloat16* __restrict__ vh, const __nv_bfloat16* __restrict__ vl,
    float* __restrict__ Ol, float* __restrict__ Ml, float* __restrict__ Sl)
{
    extern __shared__ __align__(16) char smraw[];
    const uint32_t sb = smem_u32(smraw);
    const int qt   = blockIdx.x;
    const int h    = blockIdx.y;
    const int b    = blockIdx.z;
    const int base = qt * 64;
    const int tid  = threadIdx.x;
    const int lane = tid & 31, wid = tid >> 5;
    const int wm = wid >> 2, wn = wid & 3;

    float* REDMAX = (float*)(smraw + SM_REDMAX);
    float* REDSUM = (float*)(smraw + SM_REDSUM);

    #define ROWOFF(p) ((size_t)((b * SEQ + (p)) * HEADS + h) * HD)

    // stage Q hi/lo
    for (int idx = tid; idx < 1024; idx += 256) {
        int buf = idx >> 9, rem = idx & 511;
        int i = rem >> 3, seg = rem & 7;
        const __nv_bfloat16* src = (buf ? ql : qh) + ROWOFF(base + i) + seg * 8;
        CP_ASYNC16(sb + SM_QH + buf * 9216 + i * 144 + seg * 16,
                   __cvta_generic_to_global(src));
    }
    // stage K/V window hi/lo
    for (int idx = tid; idx < 4096; idx += 256) {
        int buf = idx >> 10, rem = idx & 1023;
        int t = rem >> 3, seg = rem & 7;
        int key = base - 64 + t;
        uint32_t dstoff = (buf == 0 ? SM_KH : buf == 1 ? SM_KL :
                           buf == 2 ? SM_VH : SM_VL) + t * 144 + seg * 16;
        if (key >= 0) {
            const __nv_bfloat16* src =
                (buf == 0 ? kh : buf == 1 ? kl : buf == 2 ? vh : vl)
                + ROWOFF(key) + seg * 8;
            CP_ASYNC16(sb + dstoff, __cvta_generic_to_global(src));
        } else {
            *(uint4*)(smraw + dstoff) = make_uint4(0, 0, 0, 0);
        }
    }
    CP_COMMIT();
    asm volatile("cp.async.wait_group 0;");
    __syncthreads();

    // S = Q @ Kwin^T (3 split passes)
    float accs[2][4][4];
    #pragma unroll
    for (int mf = 0; mf < 2; mf++)
        #pragma unroll
        for (int nf = 0; nf < 4; nf++)
            #pragma unroll
            for (int j = 0; j < 4; j++) accs[mf][nf][j] = 0.f;

    const uint32_t aQrow = (uint32_t)(wm * 32 + (lane & 15)) * 144
                         + (lane >> 4) * 16;
    const uint32_t bKrow = (uint32_t)(wn * 32 + (lane & 7)
                         + ((lane >> 3) & 1) * 8) * 144 + (lane >> 4) * 16;

    #pragma unroll
    for (int kd = 0; kd < 4; kd++) {
        const uint32_t ka = kd * 32;
        uint32_t a_h[2][4], a_l[2][4], bh4[2][4], bl4[2][4];
        LDSM4(a_h[0], sb + SM_QH + aQrow + ka);
        LDSM4(a_h[1], sb + SM_QH + aQrow + 16 * 144 + ka);
        LDSM4(a_l[0], sb + SM_QL + aQrow + ka);
        LDSM4(a_l[1], sb + SM_QL + aQrow + 16 * 144 + ka);
        #pragma unroll
        for (int g = 0; g < 2; g++) {
            LDSM4(bh4[g], sb + SM_KH + bKrow + g * 16 * 144 + ka);
            LDSM4(bl4[g], sb + SM_KL + bKrow + g * 16 * 144 + ka);
        }
        #pragma unroll
        for (int mf = 0; mf < 2; mf++)
            #pragma unroll
            for (int nf = 0; nf < 4; nf++) {
                mma_bf16(accs[mf][nf], a_h[mf],
                         bh4[nf >> 1][nf & 1], bh4[nf >> 1][2 + (nf & 1)]);
                mma_bf16(accs[mf][nf], a_l[mf],
                         bh4[nf >> 1][nf & 1], bh4[nf >> 1][2 + (nf & 1)]);
                mma_bf16(accs[mf][nf], a_h[mf],
                         bl4[nf >> 1][nf & 1], bl4[nf >> 1][2 + (nf & 1)]);
            }
    }

    // mask + per-warp row max
    #pragma unroll
    for (int mf = 0; mf < 2; mf++)
        #pragma unroll
        for (int rh = 0; rh < 2; rh++) {
            int q_l = wm * 32 + mf * 16 + rh * 8 + (lane >> 2);
            int tlo = (base == 0) ? 64 : q_l;
            int thi = q_l + 64;
            float m = NEGINF;
            #pragma unroll
            for (int nf = 0; nf < 4; nf++)
                #pragma unroll
                for (int c = 0; c < 2; c++) {
                    int t = wn * 32 + nf * 8 + (lane & 3) * 2 + c;
                    float& sv = accs[mf][nf][rh * 2 + c];
                    if (t < tlo || t > thi) sv = NEGINF;
                    m = fmaxf(m, sv);
                }
            m = fmaxf(m, __shfl_xor_sync(0xffffffffu, m, 1));
            m = fmaxf(m, __shfl_xor_sync(0xffffffffu, m, 2));
            if ((lane & 3) == 0) REDMAX[q_l * 4 + wn] = m;
        }
    __syncthreads();   // B1

    // exp fragments -> P bf16 hi/lo; row sums
    #pragma unroll
    for (int mf = 0; mf < 2; mf++)
        #pragma unroll
        for (int rh = 0; rh < 2; rh++) {
            int q_l = wm * 32 + mf * 16 + rh * 8 + (lane >> 2);
            float Mr = fmaxf(fmaxf(REDMAX[q_l * 4 + 0], REDMAX[q_l * 4 + 1]),
                             fmaxf(REDMAX[q_l * 4 + 2], REDMAX[q_l * 4 + 3]));
            float rsum = 0.f;
            #pragma unroll
            for (int nf = 0; nf < 4; nf++) {
                float p0 = __expf(accs[mf][nf][rh * 2 + 0] - Mr);
                float p1 = __expf(accs[mf][nf][rh * 2 + 1] - Mr);
                rsum += p0 + p1;
                int t0 = wn * 32 + nf * 8 + (lane & 3) * 2;
                uint32_t addr = (uint32_t)q_l * 272 + t0 * 2;
                __nv_bfloat162 hh, ll;
                hh.x = __float2bfloat16(p0);
                hh.y = __float2bfloat16(p1);
                ll.x = __float2bfloat16(p0 - __bfloat162float(hh.x));
                ll.y = __float2bfloat16(p1 - __bfloat162float(hh.y));
                *(__nv_bfloat162*)(smraw + SM_KH + addr) = hh;
                *(__nv_bfloat162*)(smraw + SM_KL + addr) = ll;
            }
            rsum += __shfl_xor_sync(0xffffffffu, rsum, 1);
            rsum += __shfl_xor_sync(0xffffffffu, rsum, 2);
            if ((lane & 3) == 0) REDSUM[q_l * 4 + wn] = rsum;
        }
    __syncthreads();   // B2

    // O = P @ Vwin (3 split passes)
    float acco[2][2][4];
    #pragma unroll
    for (int mf = 0; mf < 2; mf++)
        #pragma unroll
        for (int nf = 0; nf < 2; nf++)
            #pragma unroll
            for (int j = 0; j < 4; j++) acco[mf][nf][j] = 0.f;

    const uint32_t aProw = (uint32_t)(wm * 32 + (lane & 15)) * 272
                         + (lane >> 4) * 16;
    const uint32_t bVcol = (uint32_t)(wn * 16 + (lane >> 4) * 8) * 2;

    #pragma unroll
    for (int kt = 0; kt < 8; kt++) {
        uint32_t pa_h[2][4], pa_l[2][4], vbh[4], vbl[4];
        LDSM4(pa_h[0], sb + SM_KH + aProw + kt * 32);
        LDSM4(pa_h[1], sb + SM_KH + aProw + 16 * 272 + kt * 32);
        LDSM4(pa_l[0], sb + SM_KL + aProw + kt * 32);
        LDSM4(pa_l[1], sb + SM_KL + aProw + 16 * 272 + kt * 32);
        uint32_t vrow = (uint32_t)(kt * 16 + (lane & 15)) * 144 + bVcol;
        LDSM4T(vbh, sb + SM_VH + vrow);
        LDSM4T(vbl, sb + SM_VL + vrow);
        #pragma unroll
        for (int mf = 0; mf < 2; mf++) {
            mma_bf16(acco[mf][0], pa_h[mf], vbh[0], vbh[1]);
            mma_bf16(acco[mf][1], pa_h[mf], vbh[2], vbh[3]);
            mma_bf16(acco[mf][0], pa_h[mf], vbl[0], vbl[1]);
            mma_bf16(acco[mf][1], pa_h[mf], vbl[2], vbl[3]);
            mma_bf16(acco[mf][0], pa_l[mf], vbh[0], vbh[1]);
            mma_bf16(acco[mf][1], pa_l[mf], vbh[2], vbh[3]);
        }
    }

    // epilogue: write unnormalized O_local + per-row (max, sum)
    const int d0 = wn * 16 + (lane & 3) * 2;
    #pragma unroll
    for (int mf = 0; mf < 2; mf++)
        #pragma unroll
        for (int rh = 0; rh < 2; rh++) {
            int q_l = wm * 32 + mf * 16 + rh * 8 + (lane >> 2);
            int qpos = base + q_l;
            if (wn == 0 && (lane & 3) == 0) {
                float Mr = fmaxf(fmaxf(REDMAX[q_l * 4 + 0], REDMAX[q_l * 4 + 1]),
                                 fmaxf(REDMAX[q_l * 4 + 2], REDMAX[q_l * 4 + 3]));
                float sum = REDSUM[q_l * 4 + 0] + REDSUM[q_l * 4 + 1]
                          + REDSUM[q_l * 4 + 2] + REDSUM[q_l * 4 + 3];
                int gi = (b * SEQ + qpos) * HEADS + h;
                Ml[gi] = Mr;
                Sl[gi] = sum;
            }
            size_t off = ROWOFF(qpos) + d0;
            *(float2*)(Ol + off) =
                make_float2(acco[mf][0][rh * 2 + 0], acco[mf][0][rh * 2 + 1]);
            *(float2*)(Ol + off + 8) =
                make_float2(acco[mf][1][rh * 2 + 0], acco[mf][1][rh * 2 + 1]);
        }
    #undef ROWOFF
}

// ---------------------------------------------------------------------------
// Strided attention + flash-combine. Block = (residue r, head, batch),
// 128 threads (4 warps). Queries {64j+r}, keys {64i+r}, i <= j-2:
// S_str = 32x32x64 HMMA, PV_str = 32x64x32 HMMA; then merges with the local
// partial (Ol, Ml, Sl) and writes final bf16 hi/lo attention output.
// ---------------------------------------------------------------------------
#define ST_QH    0       // 32 x 72 bf16 (144B stride)
#define ST_QL    4608
#define ST_KH    9216
#define ST_KL    13824
#define ST_VH    18432
#define ST_VL    23040
#define ST_PH    27648   // 32 x 40 bf16 (80B stride)
#define ST_PL    30208
#define ST_RMAX  32768   // fp32 [32][4]
#define ST_RSUM  33280   // fp32 [32][4]
#define ST_TOTAL 33792

__global__ void __launch_bounds__(128) attn_strided(
    const __nv_bfloat16* __restrict__ qh, const __nv_bfloat16* __restrict__ ql,
    const __nv_bfloat16* __restrict__ kh, const __nv_bfloat16* __restrict__ kl,
    const __nv_bfloat16* __restrict__ vh, const __nv_bfloat16* __restrict__ vl,
    const float* __restrict__ Ol, const float* __restrict__ Ml,
    const float* __restrict__ Sl,
    __nv_bfloat16* __restrict__ outh, __nv_bfloat16* __restrict__ outl)
{
    __shared__ __align__(16) char ss[ST_TOTAL];
    const uint32_t sb = smem_u32(ss);
    const int r = blockIdx.x, h = blockIdx.y, b = blockIdx.z;
    const int tid = threadIdx.x, lane = tid & 31, wn = tid >> 5;

    float* RMAX = (float*)(ss + ST_RMAX);
    float* RSUM = (float*)(ss + ST_RSUM);

    #define ROWOFF(p) ((size_t)((b * SEQ + (p)) * HEADS + h) * HD)

    // stage 6 buffers x 32 rows (positions 64j + r)
    for (int idx = tid; idx < 1536; idx += 128) {
        int buf = idx >> 8, rem = idx & 255;
        int j = rem >> 3, seg = rem & 7;
        const __nv_bfloat16* bp =
            buf == 0 ? qh : buf == 1 ? ql : buf == 2 ? kh :
            buf == 3 ? kl : buf == 4 ? vh : vl;
        CP_ASYNC16(sb + buf * 4608 + j * 144 + seg * 16,
                   __cvta_generic_to_global(bp + ROWOFF(64 * j + r) + seg * 8));
    }
    CP_COMMIT();
    asm volatile("cp.async.wait_group 0;");
    __syncthreads();

    // S_str = Q @ K^T (32x32x64, 3 split passes; warp wn owns key slice of 8)
    float accs[2][4];
    #pragma unroll
    for (int mf = 0; mf < 2; mf++)
        #pragma unroll
        for (int j = 0; j < 4; j++) accs[mf][j] = 0.f;

    const uint32_t aQrow = (uint32_t)(lane & 15) * 144 + (lane >> 4) * 16;
    const uint32_t bKrow = (uint32_t)(wn * 8 + (lane & 7)) * 144
                         + (lane >> 3) * 16;

    uint32_t bh4[2][4], bl4[2][4];
    LDSM4(bh4[0], sb + ST_KH + bKrow);
    LDSM4(bh4[1], sb + ST_KH + bKrow + 64);
    LDSM4(bl4[0], sb + ST_KL + bKrow);
    LDSM4(bl4[1], sb + ST_KL + bKrow + 64);

    #pragma unroll
    for (int kd = 0; kd < 4; kd++) {
        uint32_t a_h[2][4], a_l[2][4];
        LDSM4(a_h[0], sb + ST_QH + aQrow + kd * 32);
        LDSM4(a_h[1], sb + ST_QH + aQrow + 16 * 144 + kd * 32);
        LDSM4(a_l[0], sb + ST_QL + aQrow + kd * 32);
        LDSM4(a_l[1], sb + ST_QL + aQrow + 16 * 144 + kd * 32);
        uint32_t b0h = bh4[kd >> 1][(kd & 1) * 2];
        uint32_t b1h = bh4[kd >> 1][(kd & 1) * 2 + 1];
        uint32_t b0l = bl4[kd >> 1][(kd & 1) * 2];
        uint32_t b1l = bl4[kd >> 1][(kd & 1) * 2 + 1];
        #pragma unroll
        for (int mf = 0; mf < 2; mf++) {
            mma_bf16(accs[mf], a_h[mf], b0h, b1h);
            mma_bf16(accs[mf], a_l[mf], b0h, b1h);
            mma_bf16(accs[mf], a_h[mf], b0l, b1l);
        }
    }

    // mask (i <= j-2) + per-warp row max
    #pragma unroll
    for (int mf = 0; mf < 2; mf++)
        #pragma unroll
        for (int rh = 0; rh < 2; rh++) {
            int j = mf * 16 + rh * 8 + (lane >> 2);
            float m = NEGINF;
            #pragma unroll
            for (int c = 0; c < 2; c++) {
                int i = wn * 8 + (lane & 3) * 2 + c;
                float& sv = accs[mf][rh * 2 + c];
                if (i > j - 2) sv = NEGINF;
                m = fmaxf(m, sv);
            }
            m = fmaxf(m, __shfl_xor_sync(0xffffffffu, m, 1));
            m = fmaxf(m, __shfl_xor_sync(0xffffffffu, m, 2));
            if ((lane & 3) == 0) RMAX[j * 4 + wn] = m;
        }
    __syncthreads();

    // probs (masked -> 0) -> bf16 hi/lo; row sums
    #pragma unroll
    for (int mf = 0; mf < 2; mf++)
        #pragma unroll
        for (int rh = 0; rh < 2; rh++) {
            int j = mf * 16 + rh * 8 + (lane >> 2);
            float Ms = fmaxf(fmaxf(RMAX[j * 4 + 0], RMAX[j * 4 + 1]),
                             fmaxf(RMAX[j * 4 + 2], RMAX[j * 4 + 3]));
            int i0 = wn * 8 + (lane & 3) * 2;
            float p0 = (i0 <= j - 2)
                     ? __expf(accs[mf][rh * 2 + 0] - Ms) : 0.f;
            float p1 = (i0 + 1 <= j - 2)
                     ? __expf(accs[mf][rh * 2 + 1] - Ms) : 0.f;
            float rsum = p0 + p1;
            uint32_t addr = (uint32_t)j * 80 + i0 * 2;
            __nv_bfloat162 hh, ll;
            hh.x = __float2bfloat16(p0);
            hh.y = __float2bfloat16(p1);
            ll.x = __float2bfloat16(p0 - __bfloat162float(hh.x));
            ll.y = __float2bfloat16(p1 - __bfloat162float(hh.y));
            *(__nv_bfloat162*)(ss + ST_PH + addr) = hh;
            *(__nv_bfloat162*)(ss + ST_PL + addr) = ll;
            rsum += __shfl_xor_sync(0xffffffffu, rsum, 1);
            rsum += __shfl_xor_sync(0xffffffffu, rsum, 2);
            if ((lane & 3) == 0) RSUM[j * 4 + wn] = rsum;
        }
    __syncthreads();

    // O_str = P @ V (32x64x32, 3 split passes; warp wn owns d-slice of 16)
    float acco[2][2][4];
    #pragma unroll
    for (int mf = 0; mf < 2; mf++)
        #pragma unroll
        for (int nf = 0; nf < 2; nf++)
            #pragma unroll
            for (int j = 0; j < 4; j++) acco[mf][nf][j] = 0.f;

    const uint32_t aProw = (uint32_t)(lane & 15) * 80 + (lane >> 4) * 16;
    const uint32_t bVcol = (uint32_t)(wn * 16 + (lane >> 4) * 8) * 2;

    #pragma unroll
    for (int kt = 0; kt < 2; kt++) {
        uint32_t pa_h[2][4], pa_l[2][4], vbh[4], vbl[4];
        LDSM4(pa_h[0], sb + ST_PH + aProw + kt * 32);
        LDSM4(pa_h[1], sb + ST_PH + aProw + 16 * 80 + kt * 32);
        LDSM4(pa_l[0], sb + ST_PL + aProw + kt * 32);
        LDSM4(pa_l[1], sb + ST_PL + aProw + 16 * 80 + kt * 32);
        uint32_t vrow = (uint32_t)(kt * 16 + (lane & 15)) * 144 + bVcol;
        LDSM4T(vbh, sb + ST_VH + vrow);
        LDSM4T(vbl, sb + ST_VL + vrow);
        #pragma unroll
        for (int mf = 0; mf < 2; mf++) {
            mma_bf16(acco[mf][0], pa_h[mf], vbh[0], vbh[1]);
            mma_bf16(acco[mf][1], pa_h[mf], vbh[2], vbh[3]);
            mma_bf16(acco[mf][0], pa_h[mf], vbl[0], vbl[1]);
            mma_bf16(acco[mf][1], pa_h[mf], vbl[2], vbl[3]);
            mma_bf16(acco[mf][0], pa_l[mf], vbh[0], vbh[1]);
            mma_bf16(acco[mf][1], pa_l[mf], vbh[2], vbh[3]);
        }
    }

    // combine with local partial, write final bf16 hi/lo
    #pragma unroll
    for (int mf = 0; mf < 2; mf++)
        #pragma unroll
        for (int rh = 0; rh < 2; rh++) {
            int j = mf * 16 + rh * 8 + (lane >> 2);
            int qpos = 64 * j + r;
            float m_s = fmaxf(fmaxf(RMAX[j * 4 + 0], RMAX[j * 4 + 1]),
                              fmaxf(RMAX[j * 4 + 2], RMAX[j * 4 + 3]));
            float s_s = RSUM[j * 4 + 0] + RSUM[j * 4 + 1]
                      + RSUM[j * 4 + 2] + RSUM[j * 4 + 3];
            int gi = (b * SEQ + qpos) * HEADS + h;
            float m_l = Ml[gi], s_l = Sl[gi];
            float M = fmaxf(m_l, m_s);
            float fl = __expf(m_l - M);
            float fs = __expf(m_s - M);
            float inv = 1.f / (s_l * fl + s_s * fs);
            #pragma unroll
            for (int nf = 0; nf < 2; nf++) {
                int d0 = wn * 16 + nf * 8 + (lane & 3) * 2;
                size_t off = ROWOFF(qpos) + d0;
                float2 olv = *(const float2*)(Ol + off);
                float o0 = (olv.x * fl + acco[mf][nf][rh * 2 + 0] * fs) * inv;
                float o1 = (olv.y * fl + acco[mf][nf][rh * 2 + 1] * fs) * inv;
                __nv_bfloat162 hh, ll;
                hh.x = __float2bfloat16(o0);
                hh.y = __float2bfloat16(o1);
                ll.x = __float2bfloat16(o0 - __bfloat162float(hh.x));
                ll.y = __float2bfloat16(o1 - __bfloat162float(hh.y));
                *(__nv_bfloat162*)(outh + off) = hh;
                *(__nv_bfloat162*)(outl + off) = ll;
            }
        }
    #undef ROWOFF
}

// ---------------------------------------------------------------------------
extern "C" void kernel_launch(void* const* d_in, const int* in_sizes, int n_in,
                              void* d_out, int out_size)
{
    const float* x  = (const float*)d_in[0];
    const float* wk = (const float*)d_in[1];
    const float* wq = (const float*)d_in[2];
    const float* wv = (const float*)d_in[3];
    const float* wu = (const float*)d_in[4];
    const float* bu = (const float*)d_in[5];
    float* out = (float*)d_out;

    float *ol, *ml, *sl;
    __nv_bfloat16 *xh, *xl, *ah, *al, *wth, *wtl;
    __nv_bfloat16 *qh, *ql, *kh, *kl, *vh, *vl;
    cudaGetSymbolAddress((void**)&ol,  g_ol);
    cudaGetSymbolAddress((void**)&ml,  g_ml);
    cudaGetSymbolAddress((void**)&sl,  g_sl);
    cudaGetSymbolAddress((void**)&xh,  g_xh);
    cudaGetSymbolAddress((void**)&xl,  g_xl);
    cudaGetSymbolAddress((void**)&ah,  g_ah);
    cudaGetSymbolAddress((void**)&al,  g_al);
    cudaGetSymbolAddress((void**)&wth, g_wth);
    cudaGetSymbolAddress((void**)&wtl, g_wtl);
    cudaGetSymbolAddress((void**)&qh,  g_qh);
    cudaGetSymbolAddress((void**)&ql,  g_ql);
    cudaGetSymbolAddress((void**)&kh,  g_kh);
    cudaGetSymbolAddress((void**)&kl,  g_kl);
    cudaGetSymbolAddress((void**)&vh,  g_vh);
    cudaGetSymbolAddress((void**)&vl,  g_vl);

    // 1) split x; transpose+split weights
    split_bf16_k<<<(MROWS * EMB) / 1024, 256>>>(x, xh, xl, MROWS * EMB);
    wsplit_t<<<dim3(16, 16, 4), 256>>>(wq, wk, wv, wu, wth, wtl);

    // 2) HMMA Q/K/V projections (bf16 hi/lo only)
    cudaFuncSetAttribute(proj_mma, cudaFuncAttributeMaxDynamicSharedMemorySize,
                         MMA_SMEM);
    proj_mma<<<dim3(HH / 128, MROWS / 128, 3), 256, MMA_SMEM>>>(
        xh, xl, wth, wtl, qh, ql, kh, kl, vh, vl);

    // 3a) local-window attention -> unnormalized partial + (max, sum)
    cudaFuncSetAttribute(attn_local, cudaFuncAttributeMaxDynamicSharedMemorySize,
                         ATTN_SMEM);
    attn_local<<<dim3(SEQ / 64, HEADS, BSZ), 256, ATTN_SMEM>>>(
        qh, ql, kh, kl, vh, vl, ol, ml, sl);

    // 3b) strided attention + combine -> ah/al
    attn_strided<<<dim3(64, HEADS, BSZ), 128>>>(
        qh, ql, kh, kl, vh, vl, ol, ml, sl, ah, al);

    // 4) HMMA unify projection (+bias)
    cudaFuncSetAttribute(unify_mma, cudaFuncAttributeMaxDynamicSharedMemorySize,
                         MMA_SMEM);
    unify_mma<<<dim3(EMB / 128, MROWS / 128), 256, MMA_SMEM>>>(
        ah, al, wth, wtl, out, bu);
}